// round 1
// baseline (speedup 1.0000x reference)
#include <cuda_runtime.h>
#include <cuda_bf16.h>
#include <math.h>

// Problem constants
#define BB   4
#define TT   2048
#define CC   1024
#define NH   16
#define DH   64
#define ROWS (BB * TT)        // 8192
#define FF   (4 * CC)         // 4096

// ---------------- scratch (no allocs allowed) ----------------
__device__ float g_h [ROWS * CC];
__device__ float g_q [ROWS * CC];
__device__ float g_k [ROWS * CC];
__device__ float g_v [ROWS * CC];
__device__ float g_y [ROWS * CC];
__device__ float g_x1[ROWS * CC];
__device__ float g_m [ROWS * FF];

// ---------------- LayerNorm: one block per row ----------------
__global__ void ln_kernel(const float* __restrict__ X,
                          const float* __restrict__ gam,
                          const float* __restrict__ bet,
                          float* __restrict__ out) {
    int row = blockIdx.x;
    int tid = threadIdx.x;                 // 256 threads, 4 floats each
    const float4* x4 = (const float4*)(X + (size_t)row * CC);
    float4 v = x4[tid];
    float s  = v.x + v.y + v.z + v.w;
    float ss = v.x*v.x + v.y*v.y + v.z*v.z + v.w*v.w;
    // warp reduce
    #pragma unroll
    for (int off = 16; off > 0; off >>= 1) {
        s  += __shfl_down_sync(0xffffffffu, s,  off);
        ss += __shfl_down_sync(0xffffffffu, ss, off);
    }
    __shared__ float smS[8], smQ[8];
    __shared__ float sh_mu, sh_rstd;
    int lane = tid & 31, w = tid >> 5;
    if (lane == 0) { smS[w] = s; smQ[w] = ss; }
    __syncthreads();
    if (tid == 0) {
        float ts = 0.f, tq = 0.f;
        #pragma unroll
        for (int i = 0; i < 8; i++) { ts += smS[i]; tq += smQ[i]; }
        float mu  = ts * (1.0f / CC);
        float var = tq * (1.0f / CC) - mu * mu;
        sh_mu = mu;
        sh_rstd = rsqrtf(var + 1e-5f);
    }
    __syncthreads();
    float mu = sh_mu, rstd = sh_rstd;
    float4 gv = ((const float4*)gam)[tid];
    float4 bv = ((const float4*)bet)[tid];
    float4 o;
    o.x = (v.x - mu) * rstd * gv.x + bv.x;
    o.y = (v.y - mu) * rstd * gv.y + bv.y;
    o.z = (v.z - mu) * rstd * gv.z + bv.z;
    o.w = (v.w - mu) * rstd * gv.w + bv.w;
    ((float4*)(out + (size_t)row * CC))[tid] = o;
}

// ---------------- GEMM: C[M,N] = A[M,K] @ W[K,N] + bias (+res) (+gelu) ----------------
// EPI: 0 = bias, 1 = bias + residual, 2 = bias + exact GELU
#define BM 128
#define BN 128
#define BK 8
#define TM 8
#define TN 8

__device__ __forceinline__ float gelu_exact(float x) {
    return 0.5f * x * (1.0f + erff(x * 0.70710678118654752f));
}

template <int EPI>
__global__ __launch_bounds__(256)
void gemm_kernel(const float* __restrict__ A, const float* __restrict__ W,
                 const float* __restrict__ bias, const float* __restrict__ res,
                 float* __restrict__ C, int M, int N, int K) {
    __shared__ float As[BK][BM];
    __shared__ float Ws[BK][BN];
    int tid = threadIdx.x;
    int bm = blockIdx.y * BM;
    int bn = blockIdx.x * BN;

    int arow = tid >> 1;            // 0..127
    int acol = (tid & 1) * 4;       // 0 or 4
    int wrow = tid >> 5;            // 0..7
    int wcol = (tid & 31) * 4;      // 0..124

    int ty = tid >> 4, tx = tid & 15;

    float acc[TM][TN];
    #pragma unroll
    for (int i = 0; i < TM; i++)
        #pragma unroll
        for (int j = 0; j < TN; j++) acc[i][j] = 0.f;

    const float* Aptr = A + (size_t)(bm + arow) * K + acol;
    const float* Wptr = W + (size_t)wrow * N + bn + wcol;

    for (int k0 = 0; k0 < K; k0 += BK) {
        float4 av = *(const float4*)(Aptr + k0);
        As[acol + 0][arow] = av.x;
        As[acol + 1][arow] = av.y;
        As[acol + 2][arow] = av.z;
        As[acol + 3][arow] = av.w;
        float4 wv = *(const float4*)(Wptr + (size_t)k0 * N);
        *(float4*)&Ws[wrow][wcol] = wv;
        __syncthreads();
        #pragma unroll
        for (int kk = 0; kk < BK; kk++) {
            float ra[TM], rb[TN];
            #pragma unroll
            for (int i = 0; i < TM; i++) ra[i] = As[kk][ty * TM + i];
            #pragma unroll
            for (int j = 0; j < TN; j++) rb[j] = Ws[kk][tx * TN + j];
            #pragma unroll
            for (int i = 0; i < TM; i++)
                #pragma unroll
                for (int j = 0; j < TN; j++)
                    acc[i][j] = fmaf(ra[i], rb[j], acc[i][j]);
        }
        __syncthreads();
    }

    // epilogue
    #pragma unroll
    for (int i = 0; i < TM; i++) {
        int row = bm + ty * TM + i;
        int col = bn + tx * TN;
        float* cp = C + (size_t)row * N + col;
        const float* rp = (EPI == 1) ? (res + (size_t)row * N + col) : nullptr;
        #pragma unroll
        for (int j = 0; j < TN; j++) {
            float c = acc[i][j] + bias[col + j];
            if (EPI == 1) c += rp[j];
            if (EPI == 2) c = gelu_exact(c);
            cp[j] = c;
        }
    }
}

// ---------------- Flash attention (causal), fp32 ----------------
// grid (T/64, H, B), 64 threads; thread = one query row.
__global__ void attn_kernel(const float* __restrict__ Q,
                            const float* __restrict__ K,
                            const float* __restrict__ V,
                            float* __restrict__ Y) {
    int qt = blockIdx.x;
    int h  = blockIdx.y;
    int b  = blockIdx.z;
    int tid = threadIdx.x;                  // 0..63
    int qi = qt * 64 + tid;

    __shared__ float4 Ks[64][16];
    __shared__ float4 Vs[64][16];

    const float* qptr = Q + ((size_t)(b * TT + qi) * NH + h) * DH;
    float4 qv[16];
    #pragma unroll
    for (int d = 0; d < 16; d++) qv[d] = ((const float4*)qptr)[d];

    float4 o[16];
    #pragma unroll
    for (int d = 0; d < 16; d++) o[d] = make_float4(0.f, 0.f, 0.f, 0.f);
    float mrun = -1e30f, l = 0.f;

    for (int kt = 0; kt <= qt; kt++) {
        // stage K/V tile: thread tid loads key row (kt*64 + tid)
        const float4* kp = (const float4*)(K + ((size_t)(b * TT + kt * 64 + tid) * NH + h) * DH);
        const float4* vp = (const float4*)(V + ((size_t)(b * TT + kt * 64 + tid) * NH + h) * DH);
        #pragma unroll
        for (int d = 0; d < 16; d++) { Ks[tid][d] = kp[d]; Vs[tid][d] = vp[d]; }
        __syncthreads();

        int kmax = (kt == qt) ? (tid + 1) : 64;   // #unmasked keys in tile

        for (int c0 = 0; c0 < kmax; c0 += 16) {
            float s[16];
            float mx = mrun;
            #pragma unroll
            for (int k = 0; k < 16; k++) {
                float sv = -1e30f;
                if (c0 + k < kmax) {
                    const float4* kr = Ks[c0 + k];
                    float a = 0.f;
                    #pragma unroll
                    for (int d = 0; d < 16; d++) {
                        float4 kk4 = kr[d];
                        a = fmaf(qv[d].x, kk4.x, a);
                        a = fmaf(qv[d].y, kk4.y, a);
                        a = fmaf(qv[d].z, kk4.z, a);
                        a = fmaf(qv[d].w, kk4.w, a);
                    }
                    sv = a * 0.125f;   // 1/sqrt(64)
                }
                s[k] = sv;
                mx = fmaxf(mx, sv);
            }
            float corr = expf(mrun - mx);
            l *= corr;
            #pragma unroll
            for (int d = 0; d < 16; d++) {
                o[d].x *= corr; o[d].y *= corr; o[d].z *= corr; o[d].w *= corr;
            }
            #pragma unroll
            for (int k = 0; k < 16; k++) {
                float p = expf(s[k] - mx);   // masked lanes: exp(-huge) == 0
                l += p;
                const float4* vr = Vs[c0 + k];
                #pragma unroll
                for (int d = 0; d < 16; d++) {
                    float4 vv = vr[d];
                    o[d].x = fmaf(p, vv.x, o[d].x);
                    o[d].y = fmaf(p, vv.y, o[d].y);
                    o[d].z = fmaf(p, vv.z, o[d].z);
                    o[d].w = fmaf(p, vv.w, o[d].w);
                }
            }
            mrun = mx;
        }
        __syncthreads();
    }

    float inv = 1.0f / l;
    float4* yp = (float4*)(Y + ((size_t)(b * TT + qi) * NH + h) * DH);
    #pragma unroll
    for (int d = 0; d < 16; d++) {
        float4 ov = o[d];
        ov.x *= inv; ov.y *= inv; ov.z *= inv; ov.w *= inv;
        yp[d] = ov;
    }
}

// ---------------- launcher ----------------
extern "C" void kernel_launch(void* const* d_in, const int* in_sizes, int n_in,
                              void* d_out, int out_size) {
    const float* x     = (const float*)d_in[0];
    const float* ln1_g = (const float*)d_in[1];
    const float* ln1_b = (const float*)d_in[2];
    const float* Wq    = (const float*)d_in[3];
    const float* bq    = (const float*)d_in[4];
    const float* Wk    = (const float*)d_in[5];
    const float* bk    = (const float*)d_in[6];
    const float* Wv    = (const float*)d_in[7];
    const float* bv    = (const float*)d_in[8];
    const float* Wo    = (const float*)d_in[9];
    const float* bo    = (const float*)d_in[10];
    const float* ln2_g = (const float*)d_in[11];
    const float* ln2_b = (const float*)d_in[12];
    const float* W1    = (const float*)d_in[13];
    const float* b1    = (const float*)d_in[14];
    const float* W2    = (const float*)d_in[15];
    const float* b2    = (const float*)d_in[16];
    float* out = (float*)d_out;

    float *h, *q, *k, *v, *y, *x1, *m;
    cudaGetSymbolAddress((void**)&h,  g_h);
    cudaGetSymbolAddress((void**)&q,  g_q);
    cudaGetSymbolAddress((void**)&k,  g_k);
    cudaGetSymbolAddress((void**)&v,  g_v);
    cudaGetSymbolAddress((void**)&y,  g_y);
    cudaGetSymbolAddress((void**)&x1, g_x1);
    cudaGetSymbolAddress((void**)&m,  g_m);

    dim3 gC(CC / BN, ROWS / BM);   // (8, 64)
    dim3 gF(FF / BN, ROWS / BM);   // (32, 64)

    // 1) LN1
    ln_kernel<<<ROWS, 256>>>(x, ln1_g, ln1_b, h);
    // 2) QKV projections
    gemm_kernel<0><<<gC, 256>>>(h, Wq, bq, nullptr, q, ROWS, CC, CC);
    gemm_kernel<0><<<gC, 256>>>(h, Wk, bk, nullptr, k, ROWS, CC, CC);
    gemm_kernel<0><<<gC, 256>>>(h, Wv, bv, nullptr, v, ROWS, CC, CC);
    // 3) causal attention
    attn_kernel<<<dim3(TT / 64, NH, BB), 64>>>(q, k, v, y);
    // 4) output projection + residual
    gemm_kernel<1><<<gC, 256>>>(y, Wo, bo, x, x1, ROWS, CC, CC);
    // 5) LN2
    ln_kernel<<<ROWS, 256>>>(x1, ln2_g, ln2_b, h);
    // 6) MLP
    gemm_kernel<2><<<gF, 256>>>(h, W1, b1, nullptr, m, ROWS, FF, CC);
    gemm_kernel<1><<<gC, 256>>>(m, W2, b2, x1, out, ROWS, CC, FF);
}

// round 2
// speedup vs baseline: 1.7128x; 1.7128x over previous
#include <cuda_runtime.h>
#include <cuda_bf16.h>
#include <math.h>
#include <stdint.h>

// Problem constants
#define BB   4
#define TT   2048
#define CC   1024
#define NH   16
#define DH   64
#define ROWS (BB * TT)        // 8192
#define FF   (4 * CC)         // 4096

// ---------------- scratch (no allocs allowed) ----------------
__device__ float g_h [ROWS * CC];
__device__ float g_q [ROWS * CC];
__device__ float g_k [ROWS * CC];
__device__ float g_v [ROWS * CC];
__device__ float g_y [ROWS * CC];
__device__ float g_x1[ROWS * CC];
__device__ float g_m [ROWS * FF];

// ---------------- LayerNorm: one block per row ----------------
__global__ void ln_kernel(const float* __restrict__ X,
                          const float* __restrict__ gam,
                          const float* __restrict__ bet,
                          float* __restrict__ out) {
    int row = blockIdx.x;
    int tid = threadIdx.x;                 // 256 threads, 4 floats each
    const float4* x4 = (const float4*)(X + (size_t)row * CC);
    float4 v = x4[tid];
    float s  = v.x + v.y + v.z + v.w;
    float ss = v.x*v.x + v.y*v.y + v.z*v.z + v.w*v.w;
    #pragma unroll
    for (int off = 16; off > 0; off >>= 1) {
        s  += __shfl_down_sync(0xffffffffu, s,  off);
        ss += __shfl_down_sync(0xffffffffu, ss, off);
    }
    __shared__ float smS[8], smQ[8];
    __shared__ float sh_mu, sh_rstd;
    int lane = tid & 31, w = tid >> 5;
    if (lane == 0) { smS[w] = s; smQ[w] = ss; }
    __syncthreads();
    if (tid == 0) {
        float ts = 0.f, tq = 0.f;
        #pragma unroll
        for (int i = 0; i < 8; i++) { ts += smS[i]; tq += smQ[i]; }
        float mu  = ts * (1.0f / CC);
        float var = tq * (1.0f / CC) - mu * mu;
        sh_mu = mu;
        sh_rstd = rsqrtf(var + 1e-5f);
    }
    __syncthreads();
    float mu = sh_mu, rstd = sh_rstd;
    float4 gv = ((const float4*)gam)[tid];
    float4 bv = ((const float4*)bet)[tid];
    float4 o;
    o.x = (v.x - mu) * rstd * gv.x + bv.x;
    o.y = (v.y - mu) * rstd * gv.y + bv.y;
    o.z = (v.z - mu) * rstd * gv.z + bv.z;
    o.w = (v.w - mu) * rstd * gv.w + bv.w;
    ((float4*)(out + (size_t)row * CC))[tid] = o;
}

// ---------------- TF32 tensor-core GEMM ----------------
// C[M,N] = A[M,K] @ W[K,N] + bias (+res) (+gelu)
// EPI: 0 = bias, 1 = bias + residual, 2 = bias + exact GELU
// Tile: 128x128x16, 256 threads, 8 warps (2x4), warp tile 64x32, mma.m16n8k8.tf32

__device__ __forceinline__ float gelu_exact(float x) {
    return 0.5f * x * (1.0f + erff(x * 0.70710678118654752f));
}

__device__ __forceinline__ float cvt_tf32(float x) {
    uint32_t r;
    asm("cvt.rna.tf32.f32 %0, %1;" : "=r"(r) : "f"(x));
    return __uint_as_float(r);
}

__device__ __forceinline__ void mma_tf32(float& d0, float& d1, float& d2, float& d3,
                                         uint32_t a0, uint32_t a1, uint32_t a2, uint32_t a3,
                                         uint32_t b0, uint32_t b1) {
    asm volatile(
        "mma.sync.aligned.m16n8k8.row.col.f32.tf32.tf32.f32 "
        "{%0,%1,%2,%3}, {%4,%5,%6,%7}, {%8,%9}, {%0,%1,%2,%3};"
        : "+f"(d0), "+f"(d1), "+f"(d2), "+f"(d3)
        : "r"(a0), "r"(a1), "r"(a2), "r"(a3), "r"(b0), "r"(b1));
}

#define SMS 136   // smem row stride (128 + 8): makes all fragment LDS conflict-free

template <int EPI>
__global__ __launch_bounds__(256, 2)
void gemm_tc(const float* __restrict__ A, const float* __restrict__ W,
             const float* __restrict__ bias, const float* __restrict__ res,
             float* __restrict__ C, int M, int N, int K) {
    __shared__ float As[16][SMS];   // [k][m]
    __shared__ float Ws[16][SMS];   // [k][n]

    int tid  = threadIdx.x;
    int lane = tid & 31;
    int wid  = tid >> 5;
    int warp_m = wid >> 2;          // 0..1 -> m offset *64
    int warp_n = wid & 3;           // 0..3 -> n offset *32
    int bm = blockIdx.y * 128;
    int bn = blockIdx.x * 128;

    // staging assignments
    int arow = tid >> 1;            // 0..127
    int akq  = (tid & 1) * 8;       // 0 or 8
    int wkr  = tid >> 5;            // 0..7 (and +8)
    int wcol = (tid & 31) * 4;      // 0..124

    const float* Ap  = A + (size_t)(bm + arow) * K + akq;
    const float* Wp0 = W + (size_t)wkr * N + bn + wcol;
    const float* Wp1 = W + (size_t)(wkr + 8) * N + bn + wcol;

    float acc[4][4][4];
    #pragma unroll
    for (int i = 0; i < 4; i++)
        #pragma unroll
        for (int j = 0; j < 4; j++)
            #pragma unroll
            for (int r = 0; r < 4; r++) acc[i][j][r] = 0.f;

    // prologue global fetch (k0 = 0)
    float4 ra0 = *(const float4*)(Ap);
    float4 ra1 = *(const float4*)(Ap + 4);
    float4 rw0 = *(const float4*)(Wp0);
    float4 rw1 = *(const float4*)(Wp1);

    for (int k0 = 0; k0 < K; k0 += 16) {
        // stage (with tf32 rounding) into smem
        As[akq + 0][arow] = cvt_tf32(ra0.x);
        As[akq + 1][arow] = cvt_tf32(ra0.y);
        As[akq + 2][arow] = cvt_tf32(ra0.z);
        As[akq + 3][arow] = cvt_tf32(ra0.w);
        As[akq + 4][arow] = cvt_tf32(ra1.x);
        As[akq + 5][arow] = cvt_tf32(ra1.y);
        As[akq + 6][arow] = cvt_tf32(ra1.z);
        As[akq + 7][arow] = cvt_tf32(ra1.w);
        float4 t0, t1;
        t0.x = cvt_tf32(rw0.x); t0.y = cvt_tf32(rw0.y);
        t0.z = cvt_tf32(rw0.z); t0.w = cvt_tf32(rw0.w);
        t1.x = cvt_tf32(rw1.x); t1.y = cvt_tf32(rw1.y);
        t1.z = cvt_tf32(rw1.z); t1.w = cvt_tf32(rw1.w);
        *(float4*)&Ws[wkr][wcol]     = t0;
        *(float4*)&Ws[wkr + 8][wcol] = t1;
        __syncthreads();

        // prefetch next tile while mma runs
        if (k0 + 16 < K) {
            ra0 = *(const float4*)(Ap  + k0 + 16);
            ra1 = *(const float4*)(Ap  + k0 + 20);
            rw0 = *(const float4*)(Wp0 + (size_t)(k0 + 16) * N);
            rw1 = *(const float4*)(Wp1 + (size_t)(k0 + 16) * N);
        }

        #pragma unroll
        for (int kk = 0; kk < 16; kk += 8) {
            uint32_t af[4][4];
            uint32_t bf[4][2];
            int kr = kk + (lane & 3);
            int mrow = warp_m * 64 + (lane >> 2);
            int ncol = warp_n * 32 + (lane >> 2);
            #pragma unroll
            for (int mt = 0; mt < 4; mt++) {
                int m = mrow + mt * 16;
                af[mt][0] = __float_as_uint(As[kr    ][m    ]);
                af[mt][1] = __float_as_uint(As[kr    ][m + 8]);
                af[mt][2] = __float_as_uint(As[kr + 4][m    ]);
                af[mt][3] = __float_as_uint(As[kr + 4][m + 8]);
            }
            #pragma unroll
            for (int nt = 0; nt < 4; nt++) {
                int n = ncol + nt * 8;
                bf[nt][0] = __float_as_uint(Ws[kr    ][n]);
                bf[nt][1] = __float_as_uint(Ws[kr + 4][n]);
            }
            #pragma unroll
            for (int mt = 0; mt < 4; mt++)
                #pragma unroll
                for (int nt = 0; nt < 4; nt++)
                    mma_tf32(acc[mt][nt][0], acc[mt][nt][1], acc[mt][nt][2], acc[mt][nt][3],
                             af[mt][0], af[mt][1], af[mt][2], af[mt][3],
                             bf[nt][0], bf[nt][1]);
        }
        __syncthreads();
    }

    // epilogue
    #pragma unroll
    for (int mt = 0; mt < 4; mt++) {
        int r0 = bm + warp_m * 64 + mt * 16 + (lane >> 2);
        #pragma unroll
        for (int nt = 0; nt < 4; nt++) {
            int col = bn + warp_n * 32 + nt * 8 + (lane & 3) * 2;
            float b0 = bias[col], b1 = bias[col + 1];
            // rows r0 and r0+8
            #pragma unroll
            for (int h = 0; h < 2; h++) {
                int row = r0 + h * 8;
                float v0 = acc[mt][nt][h * 2 + 0] + b0;
                float v1 = acc[mt][nt][h * 2 + 1] + b1;
                if (EPI == 1) {
                    const float* rp = res + (size_t)row * N + col;
                    v0 += rp[0]; v1 += rp[1];
                }
                if (EPI == 2) { v0 = gelu_exact(v0); v1 = gelu_exact(v1); }
                float2 o = make_float2(v0, v1);
                *(float2*)(C + (size_t)row * N + col) = o;
            }
        }
    }
}

// ---------------- Flash attention (causal), fp32 ----------------
// grid (T/64, H, B), 64 threads; thread = one query row.
__global__ void attn_kernel(const float* __restrict__ Q,
                            const float* __restrict__ K,
                            const float* __restrict__ V,
                            float* __restrict__ Y) {
    int qt = blockIdx.x;
    int h  = blockIdx.y;
    int b  = blockIdx.z;
    int tid = threadIdx.x;                  // 0..63
    int qi = qt * 64 + tid;

    __shared__ float4 Ks[64][16];
    __shared__ float4 Vs[64][16];

    const float* qptr = Q + ((size_t)(b * TT + qi) * NH + h) * DH;
    float4 qv[16];
    #pragma unroll
    for (int d = 0; d < 16; d++) qv[d] = ((const float4*)qptr)[d];

    float4 o[16];
    #pragma unroll
    for (int d = 0; d < 16; d++) o[d] = make_float4(0.f, 0.f, 0.f, 0.f);
    float mrun = -1e30f, l = 0.f;

    for (int kt = 0; kt <= qt; kt++) {
        const float4* kp = (const float4*)(K + ((size_t)(b * TT + kt * 64 + tid) * NH + h) * DH);
        const float4* vp = (const float4*)(V + ((size_t)(b * TT + kt * 64 + tid) * NH + h) * DH);
        #pragma unroll
        for (int d = 0; d < 16; d++) { Ks[tid][d] = kp[d]; Vs[tid][d] = vp[d]; }
        __syncthreads();

        int kmax = (kt == qt) ? (tid + 1) : 64;

        for (int c0 = 0; c0 < kmax; c0 += 16) {
            float s[16];
            float mx = mrun;
            #pragma unroll
            for (int k = 0; k < 16; k++) {
                float sv = -1e30f;
                if (c0 + k < kmax) {
                    const float4* kr = Ks[c0 + k];
                    float a = 0.f;
                    #pragma unroll
                    for (int d = 0; d < 16; d++) {
                        float4 kk4 = kr[d];
                        a = fmaf(qv[d].x, kk4.x, a);
                        a = fmaf(qv[d].y, kk4.y, a);
                        a = fmaf(qv[d].z, kk4.z, a);
                        a = fmaf(qv[d].w, kk4.w, a);
                    }
                    sv = a * 0.125f;
                }
                s[k] = sv;
                mx = fmaxf(mx, sv);
            }
            float corr = expf(mrun - mx);
            l *= corr;
            #pragma unroll
            for (int d = 0; d < 16; d++) {
                o[d].x *= corr; o[d].y *= corr; o[d].z *= corr; o[d].w *= corr;
            }
            #pragma unroll
            for (int k = 0; k < 16; k++) {
                float p = expf(s[k] - mx);
                l += p;
                const float4* vr = Vs[c0 + k];
                #pragma unroll
                for (int d = 0; d < 16; d++) {
                    float4 vv = vr[d];
                    o[d].x = fmaf(p, vv.x, o[d].x);
                    o[d].y = fmaf(p, vv.y, o[d].y);
                    o[d].z = fmaf(p, vv.z, o[d].z);
                    o[d].w = fmaf(p, vv.w, o[d].w);
                }
            }
            mrun = mx;
        }
        __syncthreads();
    }

    float inv = 1.0f / l;
    float4* yp = (float4*)(Y + ((size_t)(b * TT + qi) * NH + h) * DH);
    #pragma unroll
    for (int d = 0; d < 16; d++) {
        float4 ov = o[d];
        ov.x *= inv; ov.y *= inv; ov.z *= inv; ov.w *= inv;
        yp[d] = ov;
    }
}

// ---------------- launcher ----------------
extern "C" void kernel_launch(void* const* d_in, const int* in_sizes, int n_in,
                              void* d_out, int out_size) {
    const float* x     = (const float*)d_in[0];
    const float* ln1_g = (const float*)d_in[1];
    const float* ln1_b = (const float*)d_in[2];
    const float* Wq    = (const float*)d_in[3];
    const float* bq    = (const float*)d_in[4];
    const float* Wk    = (const float*)d_in[5];
    const float* bk    = (const float*)d_in[6];
    const float* Wv    = (const float*)d_in[7];
    const float* bv    = (const float*)d_in[8];
    const float* Wo    = (const float*)d_in[9];
    const float* bo    = (const float*)d_in[10];
    const float* ln2_g = (const float*)d_in[11];
    const float* ln2_b = (const float*)d_in[12];
    const float* W1    = (const float*)d_in[13];
    const float* b1    = (const float*)d_in[14];
    const float* W2    = (const float*)d_in[15];
    const float* b2    = (const float*)d_in[16];
    float* out = (float*)d_out;

    float *h, *q, *k, *v, *y, *x1, *m;
    cudaGetSymbolAddress((void**)&h,  g_h);
    cudaGetSymbolAddress((void**)&q,  g_q);
    cudaGetSymbolAddress((void**)&k,  g_k);
    cudaGetSymbolAddress((void**)&v,  g_v);
    cudaGetSymbolAddress((void**)&y,  g_y);
    cudaGetSymbolAddress((void**)&x1, g_x1);
    cudaGetSymbolAddress((void**)&m,  g_m);

    dim3 gC(CC / 128, ROWS / 128);   // (8, 64)
    dim3 gF(FF / 128, ROWS / 128);   // (32, 64)

    // 1) LN1
    ln_kernel<<<ROWS, 256>>>(x, ln1_g, ln1_b, h);
    // 2) QKV projections (tf32 tensor cores)
    gemm_tc<0><<<gC, 256>>>(h, Wq, bq, nullptr, q, ROWS, CC, CC);
    gemm_tc<0><<<gC, 256>>>(h, Wk, bk, nullptr, k, ROWS, CC, CC);
    gemm_tc<0><<<gC, 256>>>(h, Wv, bv, nullptr, v, ROWS, CC, CC);
    // 3) causal attention
    attn_kernel<<<dim3(TT / 64, NH, BB), 64>>>(q, k, v, y);
    // 4) output projection + residual
    gemm_tc<1><<<gC, 256>>>(y, Wo, bo, x, x1, ROWS, CC, CC);
    // 5) LN2
    ln_kernel<<<ROWS, 256>>>(x1, ln2_g, ln2_b, h);
    // 6) MLP
    gemm_tc<2><<<gF, 256>>>(h, W1, b1, nullptr, m, ROWS, FF, CC);
    gemm_tc<1><<<gC, 256>>>(m, W2, b2, x1, out, ROWS, CC, FF);
}

// round 3
// speedup vs baseline: 1.9325x; 1.1283x over previous
#include <cuda_runtime.h>
#include <cuda_bf16.h>
#include <math.h>
#include <stdint.h>

// Problem constants
#define BB   4
#define TT   2048
#define CC   1024
#define NH   16
#define DH   64
#define ROWS (BB * TT)        // 8192
#define FF   (4 * CC)         // 4096

// ---------------- scratch (no allocs allowed) ----------------
__device__ float g_h [ROWS * CC];
__device__ float g_q [ROWS * CC];
__device__ float g_k [ROWS * CC];
__device__ float g_v [ROWS * CC];
__device__ float g_y [ROWS * CC];
__device__ float g_x1[ROWS * CC];
__device__ float g_m [ROWS * FF];

// ---------------- common helpers ----------------
__device__ __forceinline__ float gelu_exact(float x) {
    return 0.5f * x * (1.0f + erff(x * 0.70710678118654752f));
}

__device__ __forceinline__ float cvt_tf32(float x) {
    uint32_t r;
    asm("cvt.rna.tf32.f32 %0, %1;" : "=r"(r) : "f"(x));
    return __uint_as_float(r);
}

__device__ __forceinline__ void mma_tf32(float& d0, float& d1, float& d2, float& d3,
                                         uint32_t a0, uint32_t a1, uint32_t a2, uint32_t a3,
                                         uint32_t b0, uint32_t b1) {
    asm volatile(
        "mma.sync.aligned.m16n8k8.row.col.f32.tf32.tf32.f32 "
        "{%0,%1,%2,%3}, {%4,%5,%6,%7}, {%8,%9}, {%0,%1,%2,%3};"
        : "+f"(d0), "+f"(d1), "+f"(d2), "+f"(d3)
        : "r"(a0), "r"(a1), "r"(a2), "r"(a3), "r"(b0), "r"(b1));
}

// ---------------- LayerNorm: one block per row ----------------
__global__ void ln_kernel(const float* __restrict__ X,
                          const float* __restrict__ gam,
                          const float* __restrict__ bet,
                          float* __restrict__ out) {
    int row = blockIdx.x;
    int tid = threadIdx.x;                 // 256 threads, 4 floats each
    const float4* x4 = (const float4*)(X + (size_t)row * CC);
    float4 v = x4[tid];
    float s  = v.x + v.y + v.z + v.w;
    float ss = v.x*v.x + v.y*v.y + v.z*v.z + v.w*v.w;
    #pragma unroll
    for (int off = 16; off > 0; off >>= 1) {
        s  += __shfl_down_sync(0xffffffffu, s,  off);
        ss += __shfl_down_sync(0xffffffffu, ss, off);
    }
    __shared__ float smS[8], smQ[8];
    __shared__ float sh_mu, sh_rstd;
    int lane = tid & 31, w = tid >> 5;
    if (lane == 0) { smS[w] = s; smQ[w] = ss; }
    __syncthreads();
    if (tid == 0) {
        float ts = 0.f, tq = 0.f;
        #pragma unroll
        for (int i = 0; i < 8; i++) { ts += smS[i]; tq += smQ[i]; }
        float mu  = ts * (1.0f / CC);
        float var = tq * (1.0f / CC) - mu * mu;
        sh_mu = mu;
        sh_rstd = rsqrtf(var + 1e-5f);
    }
    __syncthreads();
    float mu = sh_mu, rstd = sh_rstd;
    float4 gv = ((const float4*)gam)[tid];
    float4 bv = ((const float4*)bet)[tid];
    float4 o;
    o.x = (v.x - mu) * rstd * gv.x + bv.x;
    o.y = (v.y - mu) * rstd * gv.y + bv.y;
    o.z = (v.z - mu) * rstd * gv.z + bv.z;
    o.w = (v.w - mu) * rstd * gv.w + bv.w;
    ((float4*)(out + (size_t)row * CC))[tid] = o;
}

// ---------------- TF32 tensor-core GEMM (unchanged from R2) ----------------
#define SMS 136

template <int EPI>
__global__ __launch_bounds__(256, 2)
void gemm_tc(const float* __restrict__ A, const float* __restrict__ W,
             const float* __restrict__ bias, const float* __restrict__ res,
             float* __restrict__ C, int M, int N, int K) {
    __shared__ float As[16][SMS];   // [k][m]
    __shared__ float Ws[16][SMS];   // [k][n]

    int tid  = threadIdx.x;
    int lane = tid & 31;
    int wid  = tid >> 5;
    int warp_m = wid >> 2;
    int warp_n = wid & 3;
    int bm = blockIdx.y * 128;
    int bn = blockIdx.x * 128;

    int arow = tid >> 1;
    int akq  = (tid & 1) * 8;
    int wkr  = tid >> 5;
    int wcol = (tid & 31) * 4;

    const float* Ap  = A + (size_t)(bm + arow) * K + akq;
    const float* Wp0 = W + (size_t)wkr * N + bn + wcol;
    const float* Wp1 = W + (size_t)(wkr + 8) * N + bn + wcol;

    float acc[4][4][4];
    #pragma unroll
    for (int i = 0; i < 4; i++)
        #pragma unroll
        for (int j = 0; j < 4; j++)
            #pragma unroll
            for (int r = 0; r < 4; r++) acc[i][j][r] = 0.f;

    float4 ra0 = *(const float4*)(Ap);
    float4 ra1 = *(const float4*)(Ap + 4);
    float4 rw0 = *(const float4*)(Wp0);
    float4 rw1 = *(const float4*)(Wp1);

    for (int k0 = 0; k0 < K; k0 += 16) {
        As[akq + 0][arow] = cvt_tf32(ra0.x);
        As[akq + 1][arow] = cvt_tf32(ra0.y);
        As[akq + 2][arow] = cvt_tf32(ra0.z);
        As[akq + 3][arow] = cvt_tf32(ra0.w);
        As[akq + 4][arow] = cvt_tf32(ra1.x);
        As[akq + 5][arow] = cvt_tf32(ra1.y);
        As[akq + 6][arow] = cvt_tf32(ra1.z);
        As[akq + 7][arow] = cvt_tf32(ra1.w);
        float4 t0, t1;
        t0.x = cvt_tf32(rw0.x); t0.y = cvt_tf32(rw0.y);
        t0.z = cvt_tf32(rw0.z); t0.w = cvt_tf32(rw0.w);
        t1.x = cvt_tf32(rw1.x); t1.y = cvt_tf32(rw1.y);
        t1.z = cvt_tf32(rw1.z); t1.w = cvt_tf32(rw1.w);
        *(float4*)&Ws[wkr][wcol]     = t0;
        *(float4*)&Ws[wkr + 8][wcol] = t1;
        __syncthreads();

        if (k0 + 16 < K) {
            ra0 = *(const float4*)(Ap  + k0 + 16);
            ra1 = *(const float4*)(Ap  + k0 + 20);
            rw0 = *(const float4*)(Wp0 + (size_t)(k0 + 16) * N);
            rw1 = *(const float4*)(Wp1 + (size_t)(k0 + 16) * N);
        }

        #pragma unroll
        for (int kk = 0; kk < 16; kk += 8) {
            uint32_t af[4][4];
            uint32_t bf[4][2];
            int kr = kk + (lane & 3);
            int mrow = warp_m * 64 + (lane >> 2);
            int ncol = warp_n * 32 + (lane >> 2);
            #pragma unroll
            for (int mt = 0; mt < 4; mt++) {
                int m = mrow + mt * 16;
                af[mt][0] = __float_as_uint(As[kr    ][m    ]);
                af[mt][1] = __float_as_uint(As[kr    ][m + 8]);
                af[mt][2] = __float_as_uint(As[kr + 4][m    ]);
                af[mt][3] = __float_as_uint(As[kr + 4][m + 8]);
            }
            #pragma unroll
            for (int nt = 0; nt < 4; nt++) {
                int n = ncol + nt * 8;
                bf[nt][0] = __float_as_uint(Ws[kr    ][n]);
                bf[nt][1] = __float_as_uint(Ws[kr + 4][n]);
            }
            #pragma unroll
            for (int mt = 0; mt < 4; mt++)
                #pragma unroll
                for (int nt = 0; nt < 4; nt++)
                    mma_tf32(acc[mt][nt][0], acc[mt][nt][1], acc[mt][nt][2], acc[mt][nt][3],
                             af[mt][0], af[mt][1], af[mt][2], af[mt][3],
                             bf[nt][0], bf[nt][1]);
        }
        __syncthreads();
    }

    #pragma unroll
    for (int mt = 0; mt < 4; mt++) {
        int r0 = bm + warp_m * 64 + mt * 16 + (lane >> 2);
        #pragma unroll
        for (int nt = 0; nt < 4; nt++) {
            int col = bn + warp_n * 32 + nt * 8 + (lane & 3) * 2;
            float b0 = bias[col], b1 = bias[col + 1];
            #pragma unroll
            for (int h = 0; h < 2; h++) {
                int row = r0 + h * 8;
                float v0 = acc[mt][nt][h * 2 + 0] + b0;
                float v1 = acc[mt][nt][h * 2 + 1] + b1;
                if (EPI == 1) {
                    const float* rp = res + (size_t)row * N + col;
                    v0 += rp[0]; v1 += rp[1];
                }
                if (EPI == 2) { v0 = gelu_exact(v0); v1 = gelu_exact(v1); }
                float2 o = make_float2(v0, v1);
                *(float2*)(C + (size_t)row * N + col) = o;
            }
        }
    }
}

// ---------------- Tensor-core flash attention (causal, tf32) ----------------
// grid (T/64, H, B), 128 threads (4 warps), warp w owns query rows [16w, 16w+16).
#define KS_STR 68   // stride % 32 banks == 4 -> conflict-free A/B frag reads
#define VS_STR 72   // stride % 32 banks == 8 -> conflict-free V B-frag reads

__global__ __launch_bounds__(128)
void attn_tc_kernel(const float* __restrict__ Q,
                    const float* __restrict__ K,
                    const float* __restrict__ V,
                    float* __restrict__ Y) {
    __shared__ float KPs[64][KS_STR];  // K tile, later aliased as P tile
    __shared__ float Vs [64][VS_STR];

    int qt = blockIdx.x, h = blockIdx.y, b = blockIdx.z;
    int tid = threadIdx.x;
    int lane = tid & 31, w = tid >> 5;
    int g = lane >> 2, t = lane & 3;
    int qbase = qt * 64;
    const int hoff = h * DH;

    // ---- stage Q (scaled by 1/sqrt(D), tf32) via smem, capture fragments ----
    {
        int row = tid >> 1;
        int d0 = (tid & 1) * 32;
        const float* qp = Q + (size_t)(b * TT + qbase + row) * CC + hoff + d0;
        #pragma unroll
        for (int i = 0; i < 8; i++) {
            float4 v4 = ((const float4*)qp)[i];
            KPs[row][d0 + 4*i + 0] = cvt_tf32(v4.x * 0.125f);
            KPs[row][d0 + 4*i + 1] = cvt_tf32(v4.y * 0.125f);
            KPs[row][d0 + 4*i + 2] = cvt_tf32(v4.z * 0.125f);
            KPs[row][d0 + 4*i + 3] = cvt_tf32(v4.w * 0.125f);
        }
    }
    __syncthreads();
    uint32_t qf[8][4];
    {
        int rA = 16 * w + g;
        #pragma unroll
        for (int kc = 0; kc < 8; kc++) {
            qf[kc][0] = __float_as_uint(KPs[rA    ][kc*8 + t    ]);
            qf[kc][1] = __float_as_uint(KPs[rA + 8][kc*8 + t    ]);
            qf[kc][2] = __float_as_uint(KPs[rA    ][kc*8 + t + 4]);
            qf[kc][3] = __float_as_uint(KPs[rA + 8][kc*8 + t + 4]);
        }
    }
    __syncthreads();

    float o[8][4];
    #pragma unroll
    for (int nt = 0; nt < 8; nt++)
        #pragma unroll
        for (int j = 0; j < 4; j++) o[nt][j] = 0.f;
    float mA = -1e30f, mB = -1e30f, lA = 0.f, lB = 0.f;

    for (int kt = 0; kt <= qt; kt++) {
        // ---- load K, V tiles (tf32-converted) ----
        {
            int row = tid >> 1;
            int d0 = (tid & 1) * 32;
            const float* kp = K + (size_t)(b * TT + kt * 64 + row) * CC + hoff + d0;
            const float* vp = V + (size_t)(b * TT + kt * 64 + row) * CC + hoff + d0;
            #pragma unroll
            for (int i = 0; i < 8; i++) {
                float4 kv = ((const float4*)kp)[i];
                KPs[row][d0 + 4*i + 0] = cvt_tf32(kv.x);
                KPs[row][d0 + 4*i + 1] = cvt_tf32(kv.y);
                KPs[row][d0 + 4*i + 2] = cvt_tf32(kv.z);
                KPs[row][d0 + 4*i + 3] = cvt_tf32(kv.w);
                float4 vv = ((const float4*)vp)[i];
                Vs[row][d0 + 4*i + 0] = cvt_tf32(vv.x);
                Vs[row][d0 + 4*i + 1] = cvt_tf32(vv.y);
                Vs[row][d0 + 4*i + 2] = cvt_tf32(vv.z);
                Vs[row][d0 + 4*i + 3] = cvt_tf32(vv.w);
            }
        }
        __syncthreads();

        // ---- S = Q K^T ----
        float s[8][4];
        #pragma unroll
        for (int nt = 0; nt < 8; nt++)
            #pragma unroll
            for (int j = 0; j < 4; j++) s[nt][j] = 0.f;
        #pragma unroll
        for (int kc = 0; kc < 8; kc++) {
            #pragma unroll
            for (int nt = 0; nt < 8; nt++) {
                uint32_t b0 = __float_as_uint(KPs[nt*8 + g][kc*8 + t    ]);
                uint32_t b1 = __float_as_uint(KPs[nt*8 + g][kc*8 + t + 4]);
                mma_tf32(s[nt][0], s[nt][1], s[nt][2], s[nt][3],
                         qf[kc][0], qf[kc][1], qf[kc][2], qf[kc][3], b0, b1);
            }
        }

        int rA = 16 * w + g;       // local query rows of this thread
        int rB = rA + 8;

        // ---- causal mask on diagonal tile ----
        if (kt == qt) {
            #pragma unroll
            for (int nt = 0; nt < 8; nt++) {
                int c0 = nt * 8 + 2 * t;
                if (c0     > rA) s[nt][0] = -1e30f;
                if (c0 + 1 > rA) s[nt][1] = -1e30f;
                if (c0     > rB) s[nt][2] = -1e30f;
                if (c0 + 1 > rB) s[nt][3] = -1e30f;
            }
        }

        // ---- online softmax ----
        float mxA = -1e30f, mxB = -1e30f;
        #pragma unroll
        for (int nt = 0; nt < 8; nt++) {
            mxA = fmaxf(mxA, fmaxf(s[nt][0], s[nt][1]));
            mxB = fmaxf(mxB, fmaxf(s[nt][2], s[nt][3]));
        }
        mxA = fmaxf(mxA, __shfl_xor_sync(0xffffffffu, mxA, 1));
        mxA = fmaxf(mxA, __shfl_xor_sync(0xffffffffu, mxA, 2));
        mxB = fmaxf(mxB, __shfl_xor_sync(0xffffffffu, mxB, 1));
        mxB = fmaxf(mxB, __shfl_xor_sync(0xffffffffu, mxB, 2));
        float mnA = fmaxf(mA, mxA);
        float mnB = fmaxf(mB, mxB);
        float corrA = __expf(mA - mnA);
        float corrB = __expf(mB - mnB);

        float sumA = 0.f, sumB = 0.f;
        #pragma unroll
        for (int nt = 0; nt < 8; nt++) {
            s[nt][0] = __expf(s[nt][0] - mnA); sumA += s[nt][0];
            s[nt][1] = __expf(s[nt][1] - mnA); sumA += s[nt][1];
            s[nt][2] = __expf(s[nt][2] - mnB); sumB += s[nt][2];
            s[nt][3] = __expf(s[nt][3] - mnB); sumB += s[nt][3];
        }
        sumA += __shfl_xor_sync(0xffffffffu, sumA, 1);
        sumA += __shfl_xor_sync(0xffffffffu, sumA, 2);
        sumB += __shfl_xor_sync(0xffffffffu, sumB, 1);
        sumB += __shfl_xor_sync(0xffffffffu, sumB, 2);
        lA = lA * corrA + sumA;
        lB = lB * corrB + sumB;
        mA = mnA; mB = mnB;

        #pragma unroll
        for (int nt = 0; nt < 8; nt++) {
            o[nt][0] *= corrA; o[nt][1] *= corrA;
            o[nt][2] *= corrB; o[nt][3] *= corrB;
        }

        // ---- all warps done reading K; alias KPs as P tile ----
        __syncthreads();
        #pragma unroll
        for (int nt = 0; nt < 8; nt++) {
            int c0 = nt * 8 + 2 * t;
            KPs[rA][c0    ] = cvt_tf32(s[nt][0]);
            KPs[rA][c0 + 1] = cvt_tf32(s[nt][1]);
            KPs[rB][c0    ] = cvt_tf32(s[nt][2]);
            KPs[rB][c0 + 1] = cvt_tf32(s[nt][3]);
        }
        __syncwarp();

        // ---- O += P V ----
        #pragma unroll
        for (int kc = 0; kc < 8; kc++) {
            uint32_t a0 = __float_as_uint(KPs[rA][kc*8 + t    ]);
            uint32_t a1 = __float_as_uint(KPs[rB][kc*8 + t    ]);
            uint32_t a2 = __float_as_uint(KPs[rA][kc*8 + t + 4]);
            uint32_t a3 = __float_as_uint(KPs[rB][kc*8 + t + 4]);
            #pragma unroll
            for (int nt = 0; nt < 8; nt++) {
                uint32_t b0 = __float_as_uint(Vs[kc*8 + t    ][nt*8 + g]);
                uint32_t b1 = __float_as_uint(Vs[kc*8 + t + 4][nt*8 + g]);
                mma_tf32(o[nt][0], o[nt][1], o[nt][2], o[nt][3],
                         a0, a1, a2, a3, b0, b1);
            }
        }
        __syncthreads();   // before next tile's K/V load
    }

    // ---- epilogue ----
    float invA = 1.0f / lA, invB = 1.0f / lB;
    int rowA = qbase + 16 * w + g;
    float* yA = Y + (size_t)(b * TT + rowA) * CC + hoff;
    float* yB = Y + (size_t)(b * TT + rowA + 8) * CC + hoff;
    #pragma unroll
    for (int nt = 0; nt < 8; nt++) {
        int c0 = nt * 8 + 2 * t;
        *(float2*)(yA + c0) = make_float2(o[nt][0] * invA, o[nt][1] * invA);
        *(float2*)(yB + c0) = make_float2(o[nt][2] * invB, o[nt][3] * invB);
    }
}

// ---------------- launcher ----------------
extern "C" void kernel_launch(void* const* d_in, const int* in_sizes, int n_in,
                              void* d_out, int out_size) {
    const float* x     = (const float*)d_in[0];
    const float* ln1_g = (const float*)d_in[1];
    const float* ln1_b = (const float*)d_in[2];
    const float* Wq    = (const float*)d_in[3];
    const float* bq    = (const float*)d_in[4];
    const float* Wk    = (const float*)d_in[5];
    const float* bk    = (const float*)d_in[6];
    const float* Wv    = (const float*)d_in[7];
    const float* bv    = (const float*)d_in[8];
    const float* Wo    = (const float*)d_in[9];
    const float* bo    = (const float*)d_in[10];
    const float* ln2_g = (const float*)d_in[11];
    const float* ln2_b = (const float*)d_in[12];
    const float* W1    = (const float*)d_in[13];
    const float* b1    = (const float*)d_in[14];
    const float* W2    = (const float*)d_in[15];
    const float* b2    = (const float*)d_in[16];
    float* out = (float*)d_out;

    float *h, *q, *k, *v, *y, *x1, *m;
    cudaGetSymbolAddress((void**)&h,  g_h);
    cudaGetSymbolAddress((void**)&q,  g_q);
    cudaGetSymbolAddress((void**)&k,  g_k);
    cudaGetSymbolAddress((void**)&v,  g_v);
    cudaGetSymbolAddress((void**)&y,  g_y);
    cudaGetSymbolAddress((void**)&x1, g_x1);
    cudaGetSymbolAddress((void**)&m,  g_m);

    dim3 gC(CC / 128, ROWS / 128);   // (8, 64)
    dim3 gF(FF / 128, ROWS / 128);   // (32, 64)

    // 1) LN1
    ln_kernel<<<ROWS, 256>>>(x, ln1_g, ln1_b, h);
    // 2) QKV projections (tf32 tensor cores)
    gemm_tc<0><<<gC, 256>>>(h, Wq, bq, nullptr, q, ROWS, CC, CC);
    gemm_tc<0><<<gC, 256>>>(h, Wk, bk, nullptr, k, ROWS, CC, CC);
    gemm_tc<0><<<gC, 256>>>(h, Wv, bv, nullptr, v, ROWS, CC, CC);
    // 3) causal attention (tf32 tensor cores)
    attn_tc_kernel<<<dim3(TT / 64, NH, BB), 128>>>(q, k, v, y);
    // 4) output projection + residual
    gemm_tc<1><<<gC, 256>>>(y, Wo, bo, x, x1, ROWS, CC, CC);
    // 5) LN2
    ln_kernel<<<ROWS, 256>>>(x1, ln2_g, ln2_b, h);
    // 6) MLP
    gemm_tc<2><<<gF, 256>>>(h, W1, b1, nullptr, m, ROWS, FF, CC);
    gemm_tc<1><<<gC, 256>>>(m, W2, b2, x1, out, ROWS, CC, FF);
}

// round 4
// speedup vs baseline: 2.7462x; 1.4210x over previous
#include <cuda_runtime.h>
#include <cuda_bf16.h>
#include <math.h>
#include <stdint.h>

// Problem constants
#define BB   4
#define TT   2048
#define CC   1024
#define NH   16
#define DH   64
#define ROWS (BB * TT)        // 8192
#define FF   (4 * CC)         // 4096

// ---------------- scratch (no allocs allowed) ----------------
__device__ float g_h [ROWS * CC];
__device__ float g_q [ROWS * CC];
__device__ float g_k [ROWS * CC];
__device__ float g_v [ROWS * CC];
__device__ float g_y [ROWS * CC];
__device__ float g_x1[ROWS * CC];
__device__ float g_m [ROWS * FF];

// ---------------- common helpers ----------------
__device__ __forceinline__ float gelu_exact(float x) {
    return 0.5f * x * (1.0f + erff(x * 0.70710678118654752f));
}

__device__ __forceinline__ float cvt_tf32(float x) {
    uint32_t r;
    asm("cvt.rna.tf32.f32 %0, %1;" : "=r"(r) : "f"(x));
    return __uint_as_float(r);
}

__device__ __forceinline__ void mma_tf32(float& d0, float& d1, float& d2, float& d3,
                                         uint32_t a0, uint32_t a1, uint32_t a2, uint32_t a3,
                                         uint32_t b0, uint32_t b1) {
    asm volatile(
        "mma.sync.aligned.m16n8k8.row.col.f32.tf32.tf32.f32 "
        "{%0,%1,%2,%3}, {%4,%5,%6,%7}, {%8,%9}, {%0,%1,%2,%3};"
        : "+f"(d0), "+f"(d1), "+f"(d2), "+f"(d3)
        : "r"(a0), "r"(a1), "r"(a2), "r"(a3), "r"(b0), "r"(b1));
}

// ---------------- LayerNorm: one block per row ----------------
__global__ void ln_kernel(const float* __restrict__ X,
                          const float* __restrict__ gam,
                          const float* __restrict__ bet,
                          float* __restrict__ out) {
    int row = blockIdx.x;
    int tid = threadIdx.x;                 // 256 threads, 4 floats each
    const float4* x4 = (const float4*)(X + (size_t)row * CC);
    float4 v = x4[tid];
    float s  = v.x + v.y + v.z + v.w;
    float ss = v.x*v.x + v.y*v.y + v.z*v.z + v.w*v.w;
    #pragma unroll
    for (int off = 16; off > 0; off >>= 1) {
        s  += __shfl_down_sync(0xffffffffu, s,  off);
        ss += __shfl_down_sync(0xffffffffu, ss, off);
    }
    __shared__ float smS[8], smQ[8];
    __shared__ float sh_mu, sh_rstd;
    int lane = tid & 31, w = tid >> 5;
    if (lane == 0) { smS[w] = s; smQ[w] = ss; }
    __syncthreads();
    if (tid == 0) {
        float ts = 0.f, tq = 0.f;
        #pragma unroll
        for (int i = 0; i < 8; i++) { ts += smS[i]; tq += smQ[i]; }
        float mu  = ts * (1.0f / CC);
        float var = tq * (1.0f / CC) - mu * mu;
        sh_mu = mu;
        sh_rstd = rsqrtf(var + 1e-5f);
    }
    __syncthreads();
    float mu = sh_mu, rstd = sh_rstd;
    float4 gv = ((const float4*)gam)[tid];
    float4 bv = ((const float4*)bet)[tid];
    float4 o;
    o.x = (v.x - mu) * rstd * gv.x + bv.x;
    o.y = (v.y - mu) * rstd * gv.y + bv.y;
    o.z = (v.z - mu) * rstd * gv.z + bv.z;
    o.w = (v.w - mu) * rstd * gv.w + bv.w;
    ((float4*)(out + (size_t)row * CC))[tid] = o;
}

// ---------------- TF32 tensor-core GEMM v3 ----------------
// C[M,N] = A[M,K] @ W[K,N] + bias (+res) (+gelu)
// Fragment-permuted smem layouts + 2-stage double buffering.
// Tile: 128x128x16, 256 threads, 8 warps (2x4), warp tile 64x32.

// PA: [kc(2)][mtile(8)][lane(32)*4 + reg], mtile stride 132 floats (pad 4)
// PB: [kc(2)][ntile(16)][lane(32)*2 + reg], ntile stride 66 floats (pad 2)
#define PA_MT_STR 132
#define PA_KC_STR (8 * PA_MT_STR)     // 1056
#define PA_SIZE   (2 * PA_KC_STR)     // 2112 floats
#define PB_NT_STR 66
#define PB_KC_STR (16 * PB_NT_STR)    // 1056
#define PB_SIZE   (2 * PB_KC_STR)     // 2112 floats

template <int EPI>
__global__ __launch_bounds__(256, 2)
void gemm_tc(const float* __restrict__ A, const float* __restrict__ W,
             const float* __restrict__ bias, const float* __restrict__ res,
             float* __restrict__ C, int M, int N, int K) {
    __shared__ __align__(16) float PA[2][PA_SIZE];
    __shared__ __align__(16) float PB[2][PB_SIZE];

    int tid  = threadIdx.x;
    int lane = tid & 31;
    int wid  = tid >> 5;
    int warp_m = wid >> 2;          // 0..1
    int warp_n = wid & 3;           // 0..3
    int bm = blockIdx.y * 128;
    int bn = blockIdx.x * 128;

    // ---- staging assignments ----
    int arow = tid >> 1;            // 0..127
    int akq  = (tid & 1) * 8;       // 0 or 8
    int wkr  = tid >> 5;            // 0..7 (rows wkr, wkr+8)
    int wcol = (tid & 31) * 4;      // 0..124

    const float* Ap  = A + (size_t)(bm + arow) * K + akq;
    const float* Wp0 = W + (size_t)wkr * N + bn + wcol;
    const float* Wp1 = W + (size_t)(wkr + 8) * N + bn + wcol;

    // precomputed scatter indices for A staging: element j (k = akq + j)
    int a_kc = (tid & 1);
    int a_mt = arow >> 4;
    int a_m8 = (arow >> 3) & 1;
    int a_base = a_kc * PA_KC_STR + a_mt * PA_MT_STR + ((arow & 7) * 4) * 4 + a_m8;
    // idx(j) = a_base + (j&3)*4 + 2*((j>>2)&1)   [j in 0..7]

    // W staging: element (h, j): k = wkr + 8h, n = wcol + j
    int w_t   = wkr & 3;
    int w_reg = (wkr >> 2) & 1;
    // idx(h,j) = h*PB_KC_STR + ((wcol+j)>>3)*PB_NT_STR + (((wcol+j)&7)*4 + w_t)*2 + w_reg

    float acc[4][4][4];
    #pragma unroll
    for (int i = 0; i < 4; i++)
        #pragma unroll
        for (int j = 0; j < 4; j++)
            #pragma unroll
            for (int r = 0; r < 4; r++) acc[i][j][r] = 0.f;

    // ---- prologue: fetch + stage tile 0 ----
    float4 ra0 = *(const float4*)(Ap);
    float4 ra1 = *(const float4*)(Ap + 4);
    float4 rw0 = *(const float4*)(Wp0);
    float4 rw1 = *(const float4*)(Wp1);

    {
        float av[8] = {ra0.x, ra0.y, ra0.z, ra0.w, ra1.x, ra1.y, ra1.z, ra1.w};
        #pragma unroll
        for (int j = 0; j < 8; j++)
            PA[0][a_base + (j & 3) * 4 + 2 * ((j >> 2) & 1)] = cvt_tf32(av[j]);
        float wv0[4] = {rw0.x, rw0.y, rw0.z, rw0.w};
        float wv1[4] = {rw1.x, rw1.y, rw1.z, rw1.w};
        #pragma unroll
        for (int j = 0; j < 4; j++) {
            int n = wcol + j;
            int bidx = (n >> 3) * PB_NT_STR + ((n & 7) * 4 + w_t) * 2 + w_reg;
            PB[0][bidx] = cvt_tf32(wv0[j]);
            PB[0][PB_KC_STR + bidx] = cvt_tf32(wv1[j]);
        }
    }
    __syncthreads();

    int stage = 0;
    for (int k0 = 0; k0 < K; k0 += 16) {
        bool more = (k0 + 16 < K);
        if (more) {
            ra0 = *(const float4*)(Ap  + k0 + 16);
            ra1 = *(const float4*)(Ap  + k0 + 20);
            rw0 = *(const float4*)(Wp0 + (size_t)(k0 + 16) * N);
            rw1 = *(const float4*)(Wp1 + (size_t)(k0 + 16) * N);
        }

        // ---- compute on current stage ----
        #pragma unroll
        for (int kc = 0; kc < 2; kc++) {
            float4 af4[4];
            float2 bf2[4];
            #pragma unroll
            for (int mtl = 0; mtl < 4; mtl++) {
                int mt = warp_m * 4 + mtl;
                af4[mtl] = *(const float4*)&PA[stage][kc * PA_KC_STR + mt * PA_MT_STR + lane * 4];
            }
            #pragma unroll
            for (int ntl = 0; ntl < 4; ntl++) {
                int nt = warp_n * 4 + ntl;
                bf2[ntl] = *(const float2*)&PB[stage][kc * PB_KC_STR + nt * PB_NT_STR + lane * 2];
            }
            #pragma unroll
            for (int mtl = 0; mtl < 4; mtl++)
                #pragma unroll
                for (int ntl = 0; ntl < 4; ntl++)
                    mma_tf32(acc[mtl][ntl][0], acc[mtl][ntl][1], acc[mtl][ntl][2], acc[mtl][ntl][3],
                             __float_as_uint(af4[mtl].x), __float_as_uint(af4[mtl].y),
                             __float_as_uint(af4[mtl].z), __float_as_uint(af4[mtl].w),
                             __float_as_uint(bf2[ntl].x), __float_as_uint(bf2[ntl].y));
        }

        if (more) {
            int ns = stage ^ 1;
            float av[8] = {ra0.x, ra0.y, ra0.z, ra0.w, ra1.x, ra1.y, ra1.z, ra1.w};
            #pragma unroll
            for (int j = 0; j < 8; j++)
                PA[ns][a_base + (j & 3) * 4 + 2 * ((j >> 2) & 1)] = cvt_tf32(av[j]);
            float wv0[4] = {rw0.x, rw0.y, rw0.z, rw0.w};
            float wv1[4] = {rw1.x, rw1.y, rw1.z, rw1.w};
            #pragma unroll
            for (int j = 0; j < 4; j++) {
                int n = wcol + j;
                int bidx = (n >> 3) * PB_NT_STR + ((n & 7) * 4 + w_t) * 2 + w_reg;
                PB[ns][bidx] = cvt_tf32(wv0[j]);
                PB[ns][PB_KC_STR + bidx] = cvt_tf32(wv1[j]);
            }
            __syncthreads();
            stage = ns;
        }
    }

    // ---- epilogue ----
    int g = lane >> 2, t = lane & 3;
    #pragma unroll
    for (int mt = 0; mt < 4; mt++) {
        int r0 = bm + warp_m * 64 + mt * 16 + g;
        #pragma unroll
        for (int nt = 0; nt < 4; nt++) {
            int col = bn + warp_n * 32 + nt * 8 + t * 2;
            float b0 = bias[col], b1 = bias[col + 1];
            #pragma unroll
            for (int h = 0; h < 2; h++) {
                int row = r0 + h * 8;
                float v0 = acc[mt][nt][h * 2 + 0] + b0;
                float v1 = acc[mt][nt][h * 2 + 1] + b1;
                if (EPI == 1) {
                    const float* rp = res + (size_t)row * N + col;
                    v0 += rp[0]; v1 += rp[1];
                }
                if (EPI == 2) { v0 = gelu_exact(v0); v1 = gelu_exact(v1); }
                *(float2*)(C + (size_t)row * N + col) = make_float2(v0, v1);
            }
        }
    }
}

// ---------------- Tensor-core flash attention (causal, tf32) ----------------
#define KS_STR 68
#define VS_STR 72

__global__ __launch_bounds__(128)
void attn_tc_kernel(const float* __restrict__ Q,
                    const float* __restrict__ K,
                    const float* __restrict__ V,
                    float* __restrict__ Y) {
    __shared__ float KPs[64][KS_STR];
    __shared__ float Vs [64][VS_STR];

    int qt = blockIdx.x, h = blockIdx.y, b = blockIdx.z;
    int tid = threadIdx.x;
    int lane = tid & 31, w = tid >> 5;
    int g = lane >> 2, t = lane & 3;
    int qbase = qt * 64;
    const int hoff = h * DH;

    {
        int row = tid >> 1;
        int d0 = (tid & 1) * 32;
        const float* qp = Q + (size_t)(b * TT + qbase + row) * CC + hoff + d0;
        #pragma unroll
        for (int i = 0; i < 8; i++) {
            float4 v4 = ((const float4*)qp)[i];
            KPs[row][d0 + 4*i + 0] = cvt_tf32(v4.x * 0.125f);
            KPs[row][d0 + 4*i + 1] = cvt_tf32(v4.y * 0.125f);
            KPs[row][d0 + 4*i + 2] = cvt_tf32(v4.z * 0.125f);
            KPs[row][d0 + 4*i + 3] = cvt_tf32(v4.w * 0.125f);
        }
    }
    __syncthreads();
    uint32_t qf[8][4];
    {
        int rA = 16 * w + g;
        #pragma unroll
        for (int kc = 0; kc < 8; kc++) {
            qf[kc][0] = __float_as_uint(KPs[rA    ][kc*8 + t    ]);
            qf[kc][1] = __float_as_uint(KPs[rA + 8][kc*8 + t    ]);
            qf[kc][2] = __float_as_uint(KPs[rA    ][kc*8 + t + 4]);
            qf[kc][3] = __float_as_uint(KPs[rA + 8][kc*8 + t + 4]);
        }
    }
    __syncthreads();

    float o[8][4];
    #pragma unroll
    for (int nt = 0; nt < 8; nt++)
        #pragma unroll
        for (int j = 0; j < 4; j++) o[nt][j] = 0.f;
    float mA = -1e30f, mB = -1e30f, lA = 0.f, lB = 0.f;

    for (int kt = 0; kt <= qt; kt++) {
        {
            int row = tid >> 1;
            int d0 = (tid & 1) * 32;
            const float* kp = K + (size_t)(b * TT + kt * 64 + row) * CC + hoff + d0;
            const float* vp = V + (size_t)(b * TT + kt * 64 + row) * CC + hoff + d0;
            #pragma unroll
            for (int i = 0; i < 8; i++) {
                float4 kv = ((const float4*)kp)[i];
                KPs[row][d0 + 4*i + 0] = cvt_tf32(kv.x);
                KPs[row][d0 + 4*i + 1] = cvt_tf32(kv.y);
                KPs[row][d0 + 4*i + 2] = cvt_tf32(kv.z);
                KPs[row][d0 + 4*i + 3] = cvt_tf32(kv.w);
                float4 vv = ((const float4*)vp)[i];
                Vs[row][d0 + 4*i + 0] = cvt_tf32(vv.x);
                Vs[row][d0 + 4*i + 1] = cvt_tf32(vv.y);
                Vs[row][d0 + 4*i + 2] = cvt_tf32(vv.z);
                Vs[row][d0 + 4*i + 3] = cvt_tf32(vv.w);
            }
        }
        __syncthreads();

        float s[8][4];
        #pragma unroll
        for (int nt = 0; nt < 8; nt++)
            #pragma unroll
            for (int j = 0; j < 4; j++) s[nt][j] = 0.f;
        #pragma unroll
        for (int kc = 0; kc < 8; kc++) {
            #pragma unroll
            for (int nt = 0; nt < 8; nt++) {
                uint32_t b0 = __float_as_uint(KPs[nt*8 + g][kc*8 + t    ]);
                uint32_t b1 = __float_as_uint(KPs[nt*8 + g][kc*8 + t + 4]);
                mma_tf32(s[nt][0], s[nt][1], s[nt][2], s[nt][3],
                         qf[kc][0], qf[kc][1], qf[kc][2], qf[kc][3], b0, b1);
            }
        }

        int rA = 16 * w + g;
        int rB = rA + 8;

        if (kt == qt) {
            #pragma unroll
            for (int nt = 0; nt < 8; nt++) {
                int c0 = nt * 8 + 2 * t;
                if (c0     > rA) s[nt][0] = -1e30f;
                if (c0 + 1 > rA) s[nt][1] = -1e30f;
                if (c0     > rB) s[nt][2] = -1e30f;
                if (c0 + 1 > rB) s[nt][3] = -1e30f;
            }
        }

        float mxA = -1e30f, mxB = -1e30f;
        #pragma unroll
        for (int nt = 0; nt < 8; nt++) {
            mxA = fmaxf(mxA, fmaxf(s[nt][0], s[nt][1]));
            mxB = fmaxf(mxB, fmaxf(s[nt][2], s[nt][3]));
        }
        mxA = fmaxf(mxA, __shfl_xor_sync(0xffffffffu, mxA, 1));
        mxA = fmaxf(mxA, __shfl_xor_sync(0xffffffffu, mxA, 2));
        mxB = fmaxf(mxB, __shfl_xor_sync(0xffffffffu, mxB, 1));
        mxB = fmaxf(mxB, __shfl_xor_sync(0xffffffffu, mxB, 2));
        float mnA = fmaxf(mA, mxA);
        float mnB = fmaxf(mB, mxB);
        float corrA = __expf(mA - mnA);
        float corrB = __expf(mB - mnB);

        float sumA = 0.f, sumB = 0.f;
        #pragma unroll
        for (int nt = 0; nt < 8; nt++) {
            s[nt][0] = __expf(s[nt][0] - mnA); sumA += s[nt][0];
            s[nt][1] = __expf(s[nt][1] - mnA); sumA += s[nt][1];
            s[nt][2] = __expf(s[nt][2] - mnB); sumB += s[nt][2];
            s[nt][3] = __expf(s[nt][3] - mnB); sumB += s[nt][3];
        }
        sumA += __shfl_xor_sync(0xffffffffu, sumA, 1);
        sumA += __shfl_xor_sync(0xffffffffu, sumA, 2);
        sumB += __shfl_xor_sync(0xffffffffu, sumB, 1);
        sumB += __shfl_xor_sync(0xffffffffu, sumB, 2);
        lA = lA * corrA + sumA;
        lB = lB * corrB + sumB;
        mA = mnA; mB = mnB;

        #pragma unroll
        for (int nt = 0; nt < 8; nt++) {
            o[nt][0] *= corrA; o[nt][1] *= corrA;
            o[nt][2] *= corrB; o[nt][3] *= corrB;
        }

        __syncthreads();
        #pragma unroll
        for (int nt = 0; nt < 8; nt++) {
            int c0 = nt * 8 + 2 * t;
            KPs[rA][c0    ] = cvt_tf32(s[nt][0]);
            KPs[rA][c0 + 1] = cvt_tf32(s[nt][1]);
            KPs[rB][c0    ] = cvt_tf32(s[nt][2]);
            KPs[rB][c0 + 1] = cvt_tf32(s[nt][3]);
        }
        __syncwarp();

        #pragma unroll
        for (int kc = 0; kc < 8; kc++) {
            uint32_t a0 = __float_as_uint(KPs[rA][kc*8 + t    ]);
            uint32_t a1 = __float_as_uint(KPs[rB][kc*8 + t    ]);
            uint32_t a2 = __float_as_uint(KPs[rA][kc*8 + t + 4]);
            uint32_t a3 = __float_as_uint(KPs[rB][kc*8 + t + 4]);
            #pragma unroll
            for (int nt = 0; nt < 8; nt++) {
                uint32_t b0 = __float_as_uint(Vs[kc*8 + t    ][nt*8 + g]);
                uint32_t b1 = __float_as_uint(Vs[kc*8 + t + 4][nt*8 + g]);
                mma_tf32(o[nt][0], o[nt][1], o[nt][2], o[nt][3],
                         a0, a1, a2, a3, b0, b1);
            }
        }
        __syncthreads();
    }

    float invA = 1.0f / lA, invB = 1.0f / lB;
    int rowA = qbase + 16 * w + g;
    float* yA = Y + (size_t)(b * TT + rowA) * CC + hoff;
    float* yB = Y + (size_t)(b * TT + rowA + 8) * CC + hoff;
    #pragma unroll
    for (int nt = 0; nt < 8; nt++) {
        int c0 = nt * 8 + 2 * t;
        *(float2*)(yA + c0) = make_float2(o[nt][0] * invA, o[nt][1] * invA);
        *(float2*)(yB + c0) = make_float2(o[nt][2] * invB, o[nt][3] * invB);
    }
}

// ---------------- launcher ----------------
extern "C" void kernel_launch(void* const* d_in, const int* in_sizes, int n_in,
                              void* d_out, int out_size) {
    const float* x     = (const float*)d_in[0];
    const float* ln1_g = (const float*)d_in[1];
    const float* ln1_b = (const float*)d_in[2];
    const float* Wq    = (const float*)d_in[3];
    const float* bq    = (const float*)d_in[4];
    const float* Wk    = (const float*)d_in[5];
    const float* bk    = (const float*)d_in[6];
    const float* Wv    = (const float*)d_in[7];
    const float* bv    = (const float*)d_in[8];
    const float* Wo    = (const float*)d_in[9];
    const float* bo    = (const float*)d_in[10];
    const float* ln2_g = (const float*)d_in[11];
    const float* ln2_b = (const float*)d_in[12];
    const float* W1    = (const float*)d_in[13];
    const float* b1    = (const float*)d_in[14];
    const float* W2    = (const float*)d_in[15];
    const float* b2    = (const float*)d_in[16];
    float* out = (float*)d_out;

    float *h, *q, *k, *v, *y, *x1, *m;
    cudaGetSymbolAddress((void**)&h,  g_h);
    cudaGetSymbolAddress((void**)&q,  g_q);
    cudaGetSymbolAddress((void**)&k,  g_k);
    cudaGetSymbolAddress((void**)&v,  g_v);
    cudaGetSymbolAddress((void**)&y,  g_y);
    cudaGetSymbolAddress((void**)&x1, g_x1);
    cudaGetSymbolAddress((void**)&m,  g_m);

    dim3 gC(CC / 128, ROWS / 128);   // (8, 64)
    dim3 gF(FF / 128, ROWS / 128);   // (32, 64)

    ln_kernel<<<ROWS, 256>>>(x, ln1_g, ln1_b, h);
    gemm_tc<0><<<gC, 256>>>(h, Wq, bq, nullptr, q, ROWS, CC, CC);
    gemm_tc<0><<<gC, 256>>>(h, Wk, bk, nullptr, k, ROWS, CC, CC);
    gemm_tc<0><<<gC, 256>>>(h, Wv, bv, nullptr, v, ROWS, CC, CC);
    attn_tc_kernel<<<dim3(TT / 64, NH, BB), 128>>>(q, k, v, y);
    gemm_tc<1><<<gC, 256>>>(y, Wo, bo, x, x1, ROWS, CC, CC);
    ln_kernel<<<ROWS, 256>>>(x1, ln2_g, ln2_b, h);
    gemm_tc<2><<<gF, 256>>>(h, W1, b1, nullptr, m, ROWS, FF, CC);
    gemm_tc<1><<<gC, 256>>>(m, W2, b2, x1, out, ROWS, CC, FF);
}

// round 5
// speedup vs baseline: 3.3381x; 1.2155x over previous
#include <cuda_runtime.h>
#include <cuda_bf16.h>
#include <math.h>
#include <stdint.h>

// Problem constants
#define BB   4
#define TT   2048
#define CC   1024
#define NH   16
#define DH   64
#define ROWS (BB * TT)        // 8192
#define FF   (4 * CC)         // 4096

// ---------------- scratch (no allocs allowed) ----------------
__device__ float g_h [ROWS * CC];
__device__ float g_q [ROWS * CC];
__device__ float g_k [ROWS * CC];
__device__ float g_v [ROWS * CC];
__device__ float g_y [ROWS * CC];
__device__ float g_x1[ROWS * CC];
__device__ float g_m [ROWS * FF];

// ---------------- common helpers ----------------
__device__ __forceinline__ float gelu_exact(float x) {
    return 0.5f * x * (1.0f + erff(x * 0.70710678118654752f));
}

__device__ __forceinline__ float cvt_tf32(float x) {
    uint32_t r;
    asm("cvt.rna.tf32.f32 %0, %1;" : "=r"(r) : "f"(x));
    return __uint_as_float(r);
}

__device__ __forceinline__ void mma_tf32(float& d0, float& d1, float& d2, float& d3,
                                         uint32_t a0, uint32_t a1, uint32_t a2, uint32_t a3,
                                         uint32_t b0, uint32_t b1) {
    asm volatile(
        "mma.sync.aligned.m16n8k8.row.col.f32.tf32.tf32.f32 "
        "{%0,%1,%2,%3}, {%4,%5,%6,%7}, {%8,%9}, {%0,%1,%2,%3};"
        : "+f"(d0), "+f"(d1), "+f"(d2), "+f"(d3)
        : "r"(a0), "r"(a1), "r"(a2), "r"(a3), "r"(b0), "r"(b1));
}

#define CP_ASYNC16(dst, src) \
    asm volatile("cp.async.cg.shared.global [%0], [%1], 16;\n" :: "r"(dst), "l"(src))
#define CP_COMMIT() asm volatile("cp.async.commit_group;\n" ::: "memory")
#define CP_WAIT0()  asm volatile("cp.async.wait_group 0;\n" ::: "memory")

// ---------------- LayerNorm: one block per row ----------------
__global__ void ln_kernel(const float* __restrict__ X,
                          const float* __restrict__ gam,
                          const float* __restrict__ bet,
                          float* __restrict__ out) {
    int row = blockIdx.x;
    int tid = threadIdx.x;                 // 256 threads, 4 floats each
    const float4* x4 = (const float4*)(X + (size_t)row * CC);
    float4 v = x4[tid];
    float s  = v.x + v.y + v.z + v.w;
    float ss = v.x*v.x + v.y*v.y + v.z*v.z + v.w*v.w;
    #pragma unroll
    for (int off = 16; off > 0; off >>= 1) {
        s  += __shfl_down_sync(0xffffffffu, s,  off);
        ss += __shfl_down_sync(0xffffffffu, ss, off);
    }
    __shared__ float smS[8], smQ[8];
    __shared__ float sh_mu, sh_rstd;
    int lane = tid & 31, w = tid >> 5;
    if (lane == 0) { smS[w] = s; smQ[w] = ss; }
    __syncthreads();
    if (tid == 0) {
        float ts = 0.f, tq = 0.f;
        #pragma unroll
        for (int i = 0; i < 8; i++) { ts += smS[i]; tq += smQ[i]; }
        float mu  = ts * (1.0f / CC);
        float var = tq * (1.0f / CC) - mu * mu;
        sh_mu = mu;
        sh_rstd = rsqrtf(var + 1e-5f);
    }
    __syncthreads();
    float mu = sh_mu, rstd = sh_rstd;
    float4 gv = ((const float4*)gam)[tid];
    float4 bv = ((const float4*)bet)[tid];
    float4 o;
    o.x = (v.x - mu) * rstd * gv.x + bv.x;
    o.y = (v.y - mu) * rstd * gv.y + bv.y;
    o.z = (v.z - mu) * rstd * gv.z + bv.z;
    o.w = (v.w - mu) * rstd * gv.w + bv.w;
    ((float4*)(out + (size_t)row * CC))[tid] = o;
}

// ---------------- TF32 tensor-core GEMM v4: cp.async double-buffered ------
// C[M,N] = A[M,K] @ W[K,N] + bias (+res) (+gelu)
// Tile 128x128x16, 256 threads, 8 warps (2x4), warp tile 64x32.
// As: [m][k] pad to 20, Ws: [k][n] pad to 132 — 16B-aligned rows, conflict-free
// fragment reads. mma consumes raw fp32 (HW tf32 truncation).

#define AST 20
#define WST 132

template <int EPI>
__global__ __launch_bounds__(256, 2)
void gemm_tc(const float* __restrict__ A, const float* __restrict__ W,
             const float* __restrict__ bias, const float* __restrict__ res,
             float* __restrict__ C, int M, int N, int K) {
    __shared__ __align__(16) float As[2][128][AST];
    __shared__ __align__(16) float Ws[2][16][WST];

    int tid  = threadIdx.x;
    int lane = tid & 31;
    int wid  = tid >> 5;
    int warp_m = wid >> 2;          // 0..1
    int warp_n = wid & 3;           // 0..3
    int g = lane >> 2, t = lane & 3;
    int bm = blockIdx.y * 128;
    int bn = blockIdx.x * 128;

    // staging: A chunks (m, kq): thread does rows am, am+64
    int am = tid >> 2;              // 0..63
    int akq = (tid & 3) * 4;        // 0,4,8,12
    // W chunks: rows wk, wk+8
    int wk = tid >> 5;              // 0..7
    int wn4 = (tid & 31) * 4;       // 0..124

    const float* Apb = A + (size_t)(bm + am) * K + akq;
    const float* Wpb = W + (size_t)wk * N + bn + wn4;

    uint32_t sA0[2], sA1[2], sW0[2], sW1[2];
    #pragma unroll
    for (int s = 0; s < 2; s++) {
        sA0[s] = (uint32_t)__cvta_generic_to_shared(&As[s][am     ][akq]);
        sA1[s] = (uint32_t)__cvta_generic_to_shared(&As[s][am + 64][akq]);
        sW0[s] = (uint32_t)__cvta_generic_to_shared(&Ws[s][wk    ][wn4]);
        sW1[s] = (uint32_t)__cvta_generic_to_shared(&Ws[s][wk + 8][wn4]);
    }

    float acc[4][4][4];
    #pragma unroll
    for (int i = 0; i < 4; i++)
        #pragma unroll
        for (int j = 0; j < 4; j++)
            #pragma unroll
            for (int r = 0; r < 4; r++) acc[i][j][r] = 0.f;

    // prologue: issue stage 0
    {
        CP_ASYNC16(sA0[0], Apb);
        CP_ASYNC16(sA1[0], Apb + (size_t)64 * K);
        CP_ASYNC16(sW0[0], Wpb);
        CP_ASYNC16(sW1[0], Wpb + (size_t)8 * N);
        CP_COMMIT();
    }

    int NT = K >> 4;
    for (int kt = 0; kt < NT; kt++) {
        int st = kt & 1;
        CP_WAIT0();
        __syncthreads();

        // issue next stage (overlaps with compute below)
        if (kt + 1 < NT) {
            int ns = st ^ 1;
            int k0 = (kt + 1) << 4;
            CP_ASYNC16(sA0[ns], Apb + k0);
            CP_ASYNC16(sA1[ns], Apb + (size_t)64 * K + k0);
            CP_ASYNC16(sW0[ns], Wpb + (size_t)k0 * N);
            CP_ASYNC16(sW1[ns], Wpb + (size_t)(k0 + 8) * N);
        }
        CP_COMMIT();

        // compute on stage st
        #pragma unroll
        for (int kc = 0; kc < 2; kc++) {
            int kr = kc * 8 + t;
            uint32_t af[4][4];
            uint32_t bf[4][2];
            #pragma unroll
            for (int mtl = 0; mtl < 4; mtl++) {
                int m = warp_m * 64 + mtl * 16 + g;
                af[mtl][0] = __float_as_uint(As[st][m    ][kr    ]);
                af[mtl][1] = __float_as_uint(As[st][m + 8][kr    ]);
                af[mtl][2] = __float_as_uint(As[st][m    ][kr + 4]);
                af[mtl][3] = __float_as_uint(As[st][m + 8][kr + 4]);
            }
            #pragma unroll
            for (int ntl = 0; ntl < 4; ntl++) {
                int n = warp_n * 32 + ntl * 8 + g;
                bf[ntl][0] = __float_as_uint(Ws[st][kr    ][n]);
                bf[ntl][1] = __float_as_uint(Ws[st][kr + 4][n]);
            }
            #pragma unroll
            for (int mtl = 0; mtl < 4; mtl++)
                #pragma unroll
                for (int ntl = 0; ntl < 4; ntl++)
                    mma_tf32(acc[mtl][ntl][0], acc[mtl][ntl][1],
                             acc[mtl][ntl][2], acc[mtl][ntl][3],
                             af[mtl][0], af[mtl][1], af[mtl][2], af[mtl][3],
                             bf[ntl][0], bf[ntl][1]);
        }
    }

    // ---- epilogue ----
    #pragma unroll
    for (int mt = 0; mt < 4; mt++) {
        int r0 = bm + warp_m * 64 + mt * 16 + g;
        #pragma unroll
        for (int nt = 0; nt < 4; nt++) {
            int col = bn + warp_n * 32 + nt * 8 + t * 2;
            float b0 = bias[col], b1 = bias[col + 1];
            #pragma unroll
            for (int h = 0; h < 2; h++) {
                int row = r0 + h * 8;
                float v0 = acc[mt][nt][h * 2 + 0] + b0;
                float v1 = acc[mt][nt][h * 2 + 1] + b1;
                if (EPI == 1) {
                    const float* rp = res + (size_t)row * N + col;
                    v0 += rp[0]; v1 += rp[1];
                }
                if (EPI == 2) { v0 = gelu_exact(v0); v1 = gelu_exact(v1); }
                *(float2*)(C + (size_t)row * N + col) = make_float2(v0, v1);
            }
        }
    }
}

// ---------------- Tensor-core flash attention (causal, tf32) ----------------
#define KS_STR 68
#define VS_STR 72

__global__ __launch_bounds__(128)
void attn_tc_kernel(const float* __restrict__ Q,
                    const float* __restrict__ K,
                    const float* __restrict__ V,
                    float* __restrict__ Y) {
    __shared__ float KPs[64][KS_STR];
    __shared__ float Vs [64][VS_STR];

    int qt = blockIdx.x, h = blockIdx.y, b = blockIdx.z;
    int tid = threadIdx.x;
    int lane = tid & 31, w = tid >> 5;
    int g = lane >> 2, t = lane & 3;
    int qbase = qt * 64;
    const int hoff = h * DH;

    {
        int row = tid >> 1;
        int d0 = (tid & 1) * 32;
        const float* qp = Q + (size_t)(b * TT + qbase + row) * CC + hoff + d0;
        #pragma unroll
        for (int i = 0; i < 8; i++) {
            float4 v4 = ((const float4*)qp)[i];
            KPs[row][d0 + 4*i + 0] = cvt_tf32(v4.x * 0.125f);
            KPs[row][d0 + 4*i + 1] = cvt_tf32(v4.y * 0.125f);
            KPs[row][d0 + 4*i + 2] = cvt_tf32(v4.z * 0.125f);
            KPs[row][d0 + 4*i + 3] = cvt_tf32(v4.w * 0.125f);
        }
    }
    __syncthreads();
    uint32_t qf[8][4];
    {
        int rA = 16 * w + g;
        #pragma unroll
        for (int kc = 0; kc < 8; kc++) {
            qf[kc][0] = __float_as_uint(KPs[rA    ][kc*8 + t    ]);
            qf[kc][1] = __float_as_uint(KPs[rA + 8][kc*8 + t    ]);
            qf[kc][2] = __float_as_uint(KPs[rA    ][kc*8 + t + 4]);
            qf[kc][3] = __float_as_uint(KPs[rA + 8][kc*8 + t + 4]);
        }
    }
    __syncthreads();

    float o[8][4];
    #pragma unroll
    for (int nt = 0; nt < 8; nt++)
        #pragma unroll
        for (int j = 0; j < 4; j++) o[nt][j] = 0.f;
    float mA = -1e30f, mB = -1e30f, lA = 0.f, lB = 0.f;

    for (int kt = 0; kt <= qt; kt++) {
        {
            int row = tid >> 1;
            int d0 = (tid & 1) * 32;
            const float* kp = K + (size_t)(b * TT + kt * 64 + row) * CC + hoff + d0;
            const float* vp = V + (size_t)(b * TT + kt * 64 + row) * CC + hoff + d0;
            #pragma unroll
            for (int i = 0; i < 8; i++) {
                float4 kv = ((const float4*)kp)[i];
                KPs[row][d0 + 4*i + 0] = cvt_tf32(kv.x);
                KPs[row][d0 + 4*i + 1] = cvt_tf32(kv.y);
                KPs[row][d0 + 4*i + 2] = cvt_tf32(kv.z);
                KPs[row][d0 + 4*i + 3] = cvt_tf32(kv.w);
                float4 vv = ((const float4*)vp)[i];
                Vs[row][d0 + 4*i + 0] = cvt_tf32(vv.x);
                Vs[row][d0 + 4*i + 1] = cvt_tf32(vv.y);
                Vs[row][d0 + 4*i + 2] = cvt_tf32(vv.z);
                Vs[row][d0 + 4*i + 3] = cvt_tf32(vv.w);
            }
        }
        __syncthreads();

        float s[8][4];
        #pragma unroll
        for (int nt = 0; nt < 8; nt++)
            #pragma unroll
            for (int j = 0; j < 4; j++) s[nt][j] = 0.f;
        #pragma unroll
        for (int kc = 0; kc < 8; kc++) {
            #pragma unroll
            for (int nt = 0; nt < 8; nt++) {
                uint32_t b0 = __float_as_uint(KPs[nt*8 + g][kc*8 + t    ]);
                uint32_t b1 = __float_as_uint(KPs[nt*8 + g][kc*8 + t + 4]);
                mma_tf32(s[nt][0], s[nt][1], s[nt][2], s[nt][3],
                         qf[kc][0], qf[kc][1], qf[kc][2], qf[kc][3], b0, b1);
            }
        }

        int rA = 16 * w + g;
        int rB = rA + 8;

        if (kt == qt) {
            #pragma unroll
            for (int nt = 0; nt < 8; nt++) {
                int c0 = nt * 8 + 2 * t;
                if (c0     > rA) s[nt][0] = -1e30f;
                if (c0 + 1 > rA) s[nt][1] = -1e30f;
                if (c0     > rB) s[nt][2] = -1e30f;
                if (c0 + 1 > rB) s[nt][3] = -1e30f;
            }
        }

        float mxA = -1e30f, mxB = -1e30f;
        #pragma unroll
        for (int nt = 0; nt < 8; nt++) {
            mxA = fmaxf(mxA, fmaxf(s[nt][0], s[nt][1]));
            mxB = fmaxf(mxB, fmaxf(s[nt][2], s[nt][3]));
        }
        mxA = fmaxf(mxA, __shfl_xor_sync(0xffffffffu, mxA, 1));
        mxA = fmaxf(mxA, __shfl_xor_sync(0xffffffffu, mxA, 2));
        mxB = fmaxf(mxB, __shfl_xor_sync(0xffffffffu, mxB, 1));
        mxB = fmaxf(mxB, __shfl_xor_sync(0xffffffffu, mxB, 2));
        float mnA = fmaxf(mA, mxA);
        float mnB = fmaxf(mB, mxB);
        float corrA = __expf(mA - mnA);
        float corrB = __expf(mB - mnB);

        float sumA = 0.f, sumB = 0.f;
        #pragma unroll
        for (int nt = 0; nt < 8; nt++) {
            s[nt][0] = __expf(s[nt][0] - mnA); sumA += s[nt][0];
            s[nt][1] = __expf(s[nt][1] - mnA); sumA += s[nt][1];
            s[nt][2] = __expf(s[nt][2] - mnB); sumB += s[nt][2];
            s[nt][3] = __expf(s[nt][3] - mnB); sumB += s[nt][3];
        }
        sumA += __shfl_xor_sync(0xffffffffu, sumA, 1);
        sumA += __shfl_xor_sync(0xffffffffu, sumA, 2);
        sumB += __shfl_xor_sync(0xffffffffu, sumB, 1);
        sumB += __shfl_xor_sync(0xffffffffu, sumB, 2);
        lA = lA * corrA + sumA;
        lB = lB * corrB + sumB;
        mA = mnA; mB = mnB;

        #pragma unroll
        for (int nt = 0; nt < 8; nt++) {
            o[nt][0] *= corrA; o[nt][1] *= corrA;
            o[nt][2] *= corrB; o[nt][3] *= corrB;
        }

        __syncthreads();
        #pragma unroll
        for (int nt = 0; nt < 8; nt++) {
            int c0 = nt * 8 + 2 * t;
            KPs[rA][c0    ] = cvt_tf32(s[nt][0]);
            KPs[rA][c0 + 1] = cvt_tf32(s[nt][1]);
            KPs[rB][c0    ] = cvt_tf32(s[nt][2]);
            KPs[rB][c0 + 1] = cvt_tf32(s[nt][3]);
        }
        __syncwarp();

        #pragma unroll
        for (int kc = 0; kc < 8; kc++) {
            uint32_t a0 = __float_as_uint(KPs[rA][kc*8 + t    ]);
            uint32_t a1 = __float_as_uint(KPs[rB][kc*8 + t    ]);
            uint32_t a2 = __float_as_uint(KPs[rA][kc*8 + t + 4]);
            uint32_t a3 = __float_as_uint(KPs[rB][kc*8 + t + 4]);
            #pragma unroll
            for (int nt = 0; nt < 8; nt++) {
                uint32_t b0 = __float_as_uint(Vs[kc*8 + t    ][nt*8 + g]);
                uint32_t b1 = __float_as_uint(Vs[kc*8 + t + 4][nt*8 + g]);
                mma_tf32(o[nt][0], o[nt][1], o[nt][2], o[nt][3],
                         a0, a1, a2, a3, b0, b1);
            }
        }
        __syncthreads();
    }

    float invA = 1.0f / lA, invB = 1.0f / lB;
    int rowA = qbase + 16 * w + g;
    float* yA = Y + (size_t)(b * TT + rowA) * CC + hoff;
    float* yB = Y + (size_t)(b * TT + rowA + 8) * CC + hoff;
    #pragma unroll
    for (int nt = 0; nt < 8; nt++) {
        int c0 = nt * 8 + 2 * t;
        *(float2*)(yA + c0) = make_float2(o[nt][0] * invA, o[nt][1] * invA);
        *(float2*)(yB + c0) = make_float2(o[nt][2] * invB, o[nt][3] * invB);
    }
}

// ---------------- launcher ----------------
extern "C" void kernel_launch(void* const* d_in, const int* in_sizes, int n_in,
                              void* d_out, int out_size) {
    const float* x     = (const float*)d_in[0];
    const float* ln1_g = (const float*)d_in[1];
    const float* ln1_b = (const float*)d_in[2];
    const float* Wq    = (const float*)d_in[3];
    const float* bq    = (const float*)d_in[4];
    const float* Wk    = (const float*)d_in[5];
    const float* bk    = (const float*)d_in[6];
    const float* Wv    = (const float*)d_in[7];
    const float* bv    = (const float*)d_in[8];
    const float* Wo    = (const float*)d_in[9];
    const float* bo    = (const float*)d_in[10];
    const float* ln2_g = (const float*)d_in[11];
    const float* ln2_b = (const float*)d_in[12];
    const float* W1    = (const float*)d_in[13];
    const float* b1    = (const float*)d_in[14];
    const float* W2    = (const float*)d_in[15];
    const float* b2    = (const float*)d_in[16];
    float* out = (float*)d_out;

    float *h, *q, *k, *v, *y, *x1, *m;
    cudaGetSymbolAddress((void**)&h,  g_h);
    cudaGetSymbolAddress((void**)&q,  g_q);
    cudaGetSymbolAddress((void**)&k,  g_k);
    cudaGetSymbolAddress((void**)&v,  g_v);
    cudaGetSymbolAddress((void**)&y,  g_y);
    cudaGetSymbolAddress((void**)&x1, g_x1);
    cudaGetSymbolAddress((void**)&m,  g_m);

    dim3 gC(CC / 128, ROWS / 128);   // (8, 64)
    dim3 gF(FF / 128, ROWS / 128);   // (32, 64)

    ln_kernel<<<ROWS, 256>>>(x, ln1_g, ln1_b, h);
    gemm_tc<0><<<gC, 256>>>(h, Wq, bq, nullptr, q, ROWS, CC, CC);
    gemm_tc<0><<<gC, 256>>>(h, Wk, bk, nullptr, k, ROWS, CC, CC);
    gemm_tc<0><<<gC, 256>>>(h, Wv, bv, nullptr, v, ROWS, CC, CC);
    attn_tc_kernel<<<dim3(TT / 64, NH, BB), 128>>>(q, k, v, y);
    gemm_tc<1><<<gC, 256>>>(y, Wo, bo, x, x1, ROWS, CC, CC);
    ln_kernel<<<ROWS, 256>>>(x1, ln2_g, ln2_b, h);
    gemm_tc<2><<<gF, 256>>>(h, W1, b1, nullptr, m, ROWS, FF, CC);
    gemm_tc<1><<<gC, 256>>>(m, W2, b2, x1, out, ROWS, CC, FF);
}

// round 7
// speedup vs baseline: 3.4358x; 1.0293x over previous
#include <cuda_runtime.h>
#include <cuda_bf16.h>
#include <math.h>
#include <stdint.h>

// Problem constants
#define BB   4
#define TT   2048
#define CC   1024
#define NH   16
#define DH   64
#define ROWS (BB * TT)        // 8192
#define FF   (4 * CC)         // 4096

// ---------------- scratch (no allocs allowed) ----------------
__device__ float g_h [ROWS * CC];
__device__ float g_q [ROWS * CC];
__device__ float g_k [ROWS * CC];
__device__ float g_v [ROWS * CC];
__device__ float g_y [ROWS * CC];
__device__ float g_x1[ROWS * CC];
__device__ float g_m [ROWS * FF];
// rna-rounded weight copies
__device__ float g_wqkv[CC * 3 * CC];   // [K=1024][N=3072] (Wq|Wk|Wv)
__device__ float g_bqkv[3 * CC];
__device__ float g_wo  [CC * CC];
__device__ float g_w1  [CC * FF];
__device__ float g_w2  [FF * CC];

// ---------------- common helpers ----------------
__device__ __forceinline__ float gelu_exact(float x) {
    return 0.5f * x * (1.0f + erff(x * 0.70710678118654752f));
}

__device__ __forceinline__ float cvt_tf32(float x) {
    uint32_t r;
    asm("cvt.rna.tf32.f32 %0, %1;" : "=r"(r) : "f"(x));
    return __uint_as_float(r);
}

__device__ __forceinline__ void mma_tf32(float& d0, float& d1, float& d2, float& d3,
                                         uint32_t a0, uint32_t a1, uint32_t a2, uint32_t a3,
                                         uint32_t b0, uint32_t b1) {
    asm volatile(
        "mma.sync.aligned.m16n8k8.row.col.f32.tf32.tf32.f32 "
        "{%0,%1,%2,%3}, {%4,%5,%6,%7}, {%8,%9}, {%0,%1,%2,%3};"
        : "+f"(d0), "+f"(d1), "+f"(d2), "+f"(d3)
        : "r"(a0), "r"(a1), "r"(a2), "r"(a3), "r"(b0), "r"(b1));
}

#define CP_ASYNC16(dst, src) \
    asm volatile("cp.async.cg.shared.global [%0], [%1], 16;\n" :: "r"(dst), "l"(src))
#define CP_COMMIT() asm volatile("cp.async.commit_group;\n" ::: "memory")

// ---------------- weight prep: rna-rounded copy ----------------
__global__ void round_copy(const float* __restrict__ src, float* __restrict__ dst,
                           int n) {
    int i = (blockIdx.x * blockDim.x + threadIdx.x) * 4;
    if (i < n) {
        float4 v = *(const float4*)(src + i);
        v.x = cvt_tf32(v.x); v.y = cvt_tf32(v.y);
        v.z = cvt_tf32(v.z); v.w = cvt_tf32(v.w);
        *(float4*)(dst + i) = v;
    }
}

// copy W[K,1024] into Wcat[K,3072] at column offset, rounded
__global__ void round_copy_cat(const float* __restrict__ src, float* __restrict__ dst,
                               int K, int coloff) {
    int k = blockIdx.y;
    int n = (blockIdx.x * blockDim.x + threadIdx.x) * 4;
    float4 v = *(const float4*)(src + (size_t)k * CC + n);
    v.x = cvt_tf32(v.x); v.y = cvt_tf32(v.y);
    v.z = cvt_tf32(v.z); v.w = cvt_tf32(v.w);
    *(float4*)(dst + (size_t)k * (3 * CC) + coloff + n) = v;
}

__global__ void cat_bias(const float* __restrict__ b0, const float* __restrict__ b1,
                         const float* __restrict__ b2, float* __restrict__ dst) {
    int i = blockIdx.x * blockDim.x + threadIdx.x;
    dst[i]          = b0[i];
    dst[i + CC]     = b1[i];
    dst[i + 2 * CC] = b2[i];
}

// ---------------- LayerNorm: one block per row (rna-rounded out) --------------
__global__ void ln_kernel(const float* __restrict__ X,
                          const float* __restrict__ gam,
                          const float* __restrict__ bet,
                          float* __restrict__ out) {
    int row = blockIdx.x;
    int tid = threadIdx.x;
    const float4* x4 = (const float4*)(X + (size_t)row * CC);
    float4 v = x4[tid];
    float s  = v.x + v.y + v.z + v.w;
    float ss = v.x*v.x + v.y*v.y + v.z*v.z + v.w*v.w;
    #pragma unroll
    for (int off = 16; off > 0; off >>= 1) {
        s  += __shfl_down_sync(0xffffffffu, s,  off);
        ss += __shfl_down_sync(0xffffffffu, ss, off);
    }
    __shared__ float smS[8], smQ[8];
    __shared__ float sh_mu, sh_rstd;
    int lane = tid & 31, w = tid >> 5;
    if (lane == 0) { smS[w] = s; smQ[w] = ss; }
    __syncthreads();
    if (tid == 0) {
        float ts = 0.f, tq = 0.f;
        #pragma unroll
        for (int i = 0; i < 8; i++) { ts += smS[i]; tq += smQ[i]; }
        float mu  = ts * (1.0f / CC);
        float var = tq * (1.0f / CC) - mu * mu;
        sh_mu = mu;
        sh_rstd = rsqrtf(var + 1e-5f);
    }
    __syncthreads();
    float mu = sh_mu, rstd = sh_rstd;
    float4 gv = ((const float4*)gam)[tid];
    float4 bv = ((const float4*)bet)[tid];
    float4 o;
    o.x = cvt_tf32((v.x - mu) * rstd * gv.x + bv.x);
    o.y = cvt_tf32((v.y - mu) * rstd * gv.y + bv.y);
    o.z = cvt_tf32((v.z - mu) * rstd * gv.z + bv.z);
    o.w = cvt_tf32((v.w - mu) * rstd * gv.w + bv.w);
    ((float4*)(out + (size_t)row * CC))[tid] = o;
}

// ---------------- TF32 HMMA GEMM, 3-stage cp.async pipeline ----------------
// C = A[M,K] @ W[K,N] + bias (+res) (+gelu+round)
// Output may be split across up to 3 buffers of width outN (QKV fusion).
// Tile 128x128x16, 256 threads, 8 warps (2x4), warp tile 64x32.

#define AST 20
#define WST 132
#define GST 3
#define STG_FLOATS (128 * AST + 16 * WST)   // 4672
#define GEMM_SMEM  (GST * STG_FLOATS * 4)   // 56064 bytes

template <int EPI>
__global__ __launch_bounds__(256, 2)
void gemm_tc(const float* __restrict__ A, const float* __restrict__ W,
             const float* __restrict__ bias, const float* __restrict__ res,
             float* __restrict__ C0, float* __restrict__ C1, float* __restrict__ C2,
             int M, int N, int K, int outN) {
    extern __shared__ __align__(16) float dsm[];

    int tid  = threadIdx.x;
    int lane = tid & 31;
    int wid  = tid >> 5;
    int warp_m = wid >> 2;
    int warp_n = wid & 3;
    int g = lane >> 2, t = lane & 3;
    int bm = blockIdx.y * 128;
    int bn = blockIdx.x * 128;

    // output buffer select (QKV fusion)
    int bi = bn / outN;
    float* C = (bi == 0) ? C0 : ((bi == 1) ? C1 : C2);
    int cn = bn - bi * outN;

    // staging map
    int am  = tid >> 2;             // 0..63: rows am, am+64
    int akq = (tid & 3) * 4;        // 0,4,8,12
    int wk  = tid >> 5;             // 0..7: rows wk, wk+8
    int wn4 = (tid & 31) * 4;

    const float* Apb = A + (size_t)(bm + am) * K + akq;
    const float* Wpb = W + (size_t)wk * N + bn + wn4;

    uint32_t sA0[GST], sA1[GST], sW0[GST], sW1[GST];
    #pragma unroll
    for (int s = 0; s < GST; s++) {
        float* base = dsm + s * STG_FLOATS;
        float (*As)[AST] = (float(*)[AST])base;
        float (*Ws)[WST] = (float(*)[WST])(base + 128 * AST);
        sA0[s] = (uint32_t)__cvta_generic_to_shared(&As[am     ][akq]);
        sA1[s] = (uint32_t)__cvta_generic_to_shared(&As[am + 64][akq]);
        sW0[s] = (uint32_t)__cvta_generic_to_shared(&Ws[wk    ][wn4]);
        sW1[s] = (uint32_t)__cvta_generic_to_shared(&Ws[wk + 8][wn4]);
    }

    float acc[4][4][4];
    #pragma unroll
    for (int i = 0; i < 4; i++)
        #pragma unroll
        for (int j = 0; j < 4; j++)
            #pragma unroll
            for (int r = 0; r < 4; r++) acc[i][j][r] = 0.f;

    int NT = K >> 4;

    // prologue: issue stages 0, 1
    #pragma unroll
    for (int s = 0; s < GST - 1; s++) {
        int k0 = s << 4;
        CP_ASYNC16(sA0[s], Apb + k0);
        CP_ASYNC16(sA1[s], Apb + (size_t)64 * K + k0);
        CP_ASYNC16(sW0[s], Wpb + (size_t)k0 * N);
        CP_ASYNC16(sW1[s], Wpb + (size_t)(k0 + 8) * N);
        CP_COMMIT();
    }

    for (int kt = 0; kt < NT; kt++) {
        int st = kt % GST;
        asm volatile("cp.async.wait_group 1;" ::: "memory");
        __syncthreads();

        // issue stage kt+2
        if (kt + GST - 1 < NT) {
            int ns = (kt + GST - 1) % GST;
            int k0 = (kt + GST - 1) << 4;
            CP_ASYNC16(sA0[ns], Apb + k0);
            CP_ASYNC16(sA1[ns], Apb + (size_t)64 * K + k0);
            CP_ASYNC16(sW0[ns], Wpb + (size_t)k0 * N);
            CP_ASYNC16(sW1[ns], Wpb + (size_t)(k0 + 8) * N);
        }
        CP_COMMIT();

        float* base = dsm + st * STG_FLOATS;
        float (*As)[AST] = (float(*)[AST])base;
        float (*Ws)[WST] = (float(*)[WST])(base + 128 * AST);

        #pragma unroll
        for (int kc = 0; kc < 2; kc++) {
            int kr = kc * 8 + t;
            uint32_t af[4][4];
            uint32_t bf[4][2];
            #pragma unroll
            for (int mtl = 0; mtl < 4; mtl++) {
                int m = warp_m * 64 + mtl * 16 + g;
                af[mtl][0] = __float_as_uint(As[m    ][kr    ]);
                af[mtl][1] = __float_as_uint(As[m + 8][kr    ]);
                af[mtl][2] = __float_as_uint(As[m    ][kr + 4]);
                af[mtl][3] = __float_as_uint(As[m + 8][kr + 4]);
            }
            #pragma unroll
            for (int ntl = 0; ntl < 4; ntl++) {
                int n = warp_n * 32 + ntl * 8 + g;
                bf[ntl][0] = __float_as_uint(Ws[kr    ][n]);
                bf[ntl][1] = __float_as_uint(Ws[kr + 4][n]);
            }
            #pragma unroll
            for (int mtl = 0; mtl < 4; mtl++)
                #pragma unroll
                for (int ntl = 0; ntl < 4; ntl++)
                    mma_tf32(acc[mtl][ntl][0], acc[mtl][ntl][1],
                             acc[mtl][ntl][2], acc[mtl][ntl][3],
                             af[mtl][0], af[mtl][1], af[mtl][2], af[mtl][3],
                             bf[ntl][0], bf[ntl][1]);
        }
    }

    // ---- epilogue ----
    #pragma unroll
    for (int mt = 0; mt < 4; mt++) {
        int r0 = bm + warp_m * 64 + mt * 16 + g;
        #pragma unroll
        for (int nt = 0; nt < 4; nt++) {
            int gcol = bn + warp_n * 32 + nt * 8 + t * 2;   // bias index (global)
            int col  = cn + warp_n * 32 + nt * 8 + t * 2;   // output-buffer col
            float b0 = bias[gcol], b1 = bias[gcol + 1];
            #pragma unroll
            for (int h = 0; h < 2; h++) {
                int row = r0 + h * 8;
                float v0 = acc[mt][nt][h * 2 + 0] + b0;
                float v1 = acc[mt][nt][h * 2 + 1] + b1;
                if (EPI == 1) {
                    const float* rp = res + (size_t)row * outN + col;
                    v0 += rp[0]; v1 += rp[1];
                }
                if (EPI == 2) {
                    v0 = cvt_tf32(gelu_exact(v0));
                    v1 = cvt_tf32(gelu_exact(v1));
                }
                *(float2*)(C + (size_t)row * outN + col) = make_float2(v0, v1);
            }
        }
    }
}

// ---------------- Tensor-core flash attention (causal, tf32) ----------------
#define KS_STR 68
#define VS_STR 72

__global__ __launch_bounds__(128)
void attn_tc_kernel(const float* __restrict__ Q,
                    const float* __restrict__ K,
                    const float* __restrict__ V,
                    float* __restrict__ Y) {
    __shared__ float KPs[64][KS_STR];
    __shared__ float Vs [64][VS_STR];

    int qt = blockIdx.x, h = blockIdx.y, b = blockIdx.z;
    int tid = threadIdx.x;
    int lane = tid & 31, w = tid >> 5;
    int g = lane >> 2, t = lane & 3;
    int qbase = qt * 64;
    const int hoff = h * DH;

    {
        int row = tid >> 1;
        int d0 = (tid & 1) * 32;
        const float* qp = Q + (size_t)(b * TT + qbase + row) * CC + hoff + d0;
        #pragma unroll
        for (int i = 0; i < 8; i++) {
            float4 v4 = ((const float4*)qp)[i];
            KPs[row][d0 + 4*i + 0] = cvt_tf32(v4.x * 0.125f);
            KPs[row][d0 + 4*i + 1] = cvt_tf32(v4.y * 0.125f);
            KPs[row][d0 + 4*i + 2] = cvt_tf32(v4.z * 0.125f);
            KPs[row][d0 + 4*i + 3] = cvt_tf32(v4.w * 0.125f);
        }
    }
    __syncthreads();
    uint32_t qf[8][4];
    {
        int rA = 16 * w + g;
        #pragma unroll
        for (int kc = 0; kc < 8; kc++) {
            qf[kc][0] = __float_as_uint(KPs[rA    ][kc*8 + t    ]);
            qf[kc][1] = __float_as_uint(KPs[rA + 8][kc*8 + t    ]);
            qf[kc][2] = __float_as_uint(KPs[rA    ][kc*8 + t + 4]);
            qf[kc][3] = __float_as_uint(KPs[rA + 8][kc*8 + t + 4]);
        }
    }
    __syncthreads();

    float o[8][4];
    #pragma unroll
    for (int nt = 0; nt < 8; nt++)
        #pragma unroll
        for (int j = 0; j < 4; j++) o[nt][j] = 0.f;
    float mA = -1e30f, mB = -1e30f, lA = 0.f, lB = 0.f;

    for (int kt = 0; kt <= qt; kt++) {
        {
            int row = tid >> 1;
            int d0 = (tid & 1) * 32;
            const float* kp = K + (size_t)(b * TT + kt * 64 + row) * CC + hoff + d0;
            const float* vp = V + (size_t)(b * TT + kt * 64 + row) * CC + hoff + d0;
            #pragma unroll
            for (int i = 0; i < 8; i++) {
                float4 kv = ((const float4*)kp)[i];
                KPs[row][d0 + 4*i + 0] = cvt_tf32(kv.x);
                KPs[row][d0 + 4*i + 1] = cvt_tf32(kv.y);
                KPs[row][d0 + 4*i + 2] = cvt_tf32(kv.z);
                KPs[row][d0 + 4*i + 3] = cvt_tf32(kv.w);
                float4 vv = ((const float4*)vp)[i];
                Vs[row][d0 + 4*i + 0] = cvt_tf32(vv.x);
                Vs[row][d0 + 4*i + 1] = cvt_tf32(vv.y);
                Vs[row][d0 + 4*i + 2] = cvt_tf32(vv.z);
                Vs[row][d0 + 4*i + 3] = cvt_tf32(vv.w);
            }
        }
        __syncthreads();

        float s[8][4];
        #pragma unroll
        for (int nt = 0; nt < 8; nt++)
            #pragma unroll
            for (int j = 0; j < 4; j++) s[nt][j] = 0.f;
        #pragma unroll
        for (int kc = 0; kc < 8; kc++) {
            #pragma unroll
            for (int nt = 0; nt < 8; nt++) {
                uint32_t b0 = __float_as_uint(KPs[nt*8 + g][kc*8 + t    ]);
                uint32_t b1 = __float_as_uint(KPs[nt*8 + g][kc*8 + t + 4]);
                mma_tf32(s[nt][0], s[nt][1], s[nt][2], s[nt][3],
                         qf[kc][0], qf[kc][1], qf[kc][2], qf[kc][3], b0, b1);
            }
        }

        int rA = 16 * w + g;
        int rB = rA + 8;

        if (kt == qt) {
            #pragma unroll
            for (int nt = 0; nt < 8; nt++) {
                int c0 = nt * 8 + 2 * t;
                if (c0     > rA) s[nt][0] = -1e30f;
                if (c0 + 1 > rA) s[nt][1] = -1e30f;
                if (c0     > rB) s[nt][2] = -1e30f;
                if (c0 + 1 > rB) s[nt][3] = -1e30f;
            }
        }

        float mxA = -1e30f, mxB = -1e30f;
        #pragma unroll
        for (int nt = 0; nt < 8; nt++) {
            mxA = fmaxf(mxA, fmaxf(s[nt][0], s[nt][1]));
            mxB = fmaxf(mxB, fmaxf(s[nt][2], s[nt][3]));
        }
        mxA = fmaxf(mxA, __shfl_xor_sync(0xffffffffu, mxA, 1));
        mxA = fmaxf(mxA, __shfl_xor_sync(0xffffffffu, mxA, 2));
        mxB = fmaxf(mxB, __shfl_xor_sync(0xffffffffu, mxB, 1));
        mxB = fmaxf(mxB, __shfl_xor_sync(0xffffffffu, mxB, 2));
        float mnA = fmaxf(mA, mxA);
        float mnB = fmaxf(mB, mxB);
        float corrA = __expf(mA - mnA);
        float corrB = __expf(mB - mnB);

        float sumA = 0.f, sumB = 0.f;
        #pragma unroll
        for (int nt = 0; nt < 8; nt++) {
            s[nt][0] = __expf(s[nt][0] - mnA); sumA += s[nt][0];
            s[nt][1] = __expf(s[nt][1] - mnA); sumA += s[nt][1];
            s[nt][2] = __expf(s[nt][2] - mnB); sumB += s[nt][2];
            s[nt][3] = __expf(s[nt][3] - mnB); sumB += s[nt][3];
        }
        sumA += __shfl_xor_sync(0xffffffffu, sumA, 1);
        sumA += __shfl_xor_sync(0xffffffffu, sumA, 2);
        sumB += __shfl_xor_sync(0xffffffffu, sumB, 1);
        sumB += __shfl_xor_sync(0xffffffffu, sumB, 2);
        lA = lA * corrA + sumA;
        lB = lB * corrB + sumB;
        mA = mnA; mB = mnB;

        #pragma unroll
        for (int nt = 0; nt < 8; nt++) {
            o[nt][0] *= corrA; o[nt][1] *= corrA;
            o[nt][2] *= corrB; o[nt][3] *= corrB;
        }

        __syncthreads();
        #pragma unroll
        for (int nt = 0; nt < 8; nt++) {
            int c0 = nt * 8 + 2 * t;
            KPs[rA][c0    ] = cvt_tf32(s[nt][0]);
            KPs[rA][c0 + 1] = cvt_tf32(s[nt][1]);
            KPs[rB][c0    ] = cvt_tf32(s[nt][2]);
            KPs[rB][c0 + 1] = cvt_tf32(s[nt][3]);
        }
        __syncwarp();

        #pragma unroll
        for (int kc = 0; kc < 8; kc++) {
            uint32_t a0 = __float_as_uint(KPs[rA][kc*8 + t    ]);
            uint32_t a1 = __float_as_uint(KPs[rB][kc*8 + t    ]);
            uint32_t a2 = __float_as_uint(KPs[rA][kc*8 + t + 4]);
            uint32_t a3 = __float_as_uint(KPs[rB][kc*8 + t + 4]);
            #pragma unroll
            for (int nt = 0; nt < 8; nt++) {
                uint32_t b0 = __float_as_uint(Vs[kc*8 + t    ][nt*8 + g]);
                uint32_t b1 = __float_as_uint(Vs[kc*8 + t + 4][nt*8 + g]);
                mma_tf32(o[nt][0], o[nt][1], o[nt][2], o[nt][3],
                         a0, a1, a2, a3, b0, b1);
            }
        }
        __syncthreads();
    }

    // epilogue: rna-rounded y (feeds proj GEMM A operand)
    float invA = 1.0f / lA, invB = 1.0f / lB;
    int rowA = qbase + 16 * w + g;
    float* yA = Y + (size_t)(b * TT + rowA) * CC + hoff;
    float* yB = Y + (size_t)(b * TT + rowA + 8) * CC + hoff;
    #pragma unroll
    for (int nt = 0; nt < 8; nt++) {
        int c0 = nt * 8 + 2 * t;
        *(float2*)(yA + c0) = make_float2(cvt_tf32(o[nt][0] * invA), cvt_tf32(o[nt][1] * invA));
        *(float2*)(yB + c0) = make_float2(cvt_tf32(o[nt][2] * invB), cvt_tf32(o[nt][3] * invB));
    }
}

// ---------------- launcher ----------------
extern "C" void kernel_launch(void* const* d_in, const int* in_sizes, int n_in,
                              void* d_out, int out_size) {
    const float* x     = (const float*)d_in[0];
    const float* ln1_g = (const float*)d_in[1];
    const float* ln1_b = (const float*)d_in[2];
    const float* Wq    = (const float*)d_in[3];
    const float* bq    = (const float*)d_in[4];
    const float* Wk    = (const float*)d_in[5];
    const float* bk    = (const float*)d_in[6];
    const float* Wv    = (const float*)d_in[7];
    const float* bv    = (const float*)d_in[8];
    const float* Wo    = (const float*)d_in[9];
    const float* bo    = (const float*)d_in[10];
    const float* ln2_g = (const float*)d_in[11];
    const float* ln2_b = (const float*)d_in[12];
    const float* W1    = (const float*)d_in[13];
    const float* b1    = (const float*)d_in[14];
    const float* W2    = (const float*)d_in[15];
    const float* b2    = (const float*)d_in[16];
    float* out = (float*)d_out;

    float *h, *q, *k, *v, *y, *x1, *m;
    float *wqkv, *bqkv, *wo, *w1, *w2;
    cudaGetSymbolAddress((void**)&h,    g_h);
    cudaGetSymbolAddress((void**)&q,    g_q);
    cudaGetSymbolAddress((void**)&k,    g_k);
    cudaGetSymbolAddress((void**)&v,    g_v);
    cudaGetSymbolAddress((void**)&y,    g_y);
    cudaGetSymbolAddress((void**)&x1,   g_x1);
    cudaGetSymbolAddress((void**)&m,    g_m);
    cudaGetSymbolAddress((void**)&wqkv, g_wqkv);
    cudaGetSymbolAddress((void**)&bqkv, g_bqkv);
    cudaGetSymbolAddress((void**)&wo,   g_wo);
    cudaGetSymbolAddress((void**)&w1,   g_w1);
    cudaGetSymbolAddress((void**)&w2,   g_w2);

    cudaFuncSetAttribute(gemm_tc<0>, cudaFuncAttributeMaxDynamicSharedMemorySize, GEMM_SMEM);
    cudaFuncSetAttribute(gemm_tc<1>, cudaFuncAttributeMaxDynamicSharedMemorySize, GEMM_SMEM);
    cudaFuncSetAttribute(gemm_tc<2>, cudaFuncAttributeMaxDynamicSharedMemorySize, GEMM_SMEM);

    // 0) weight prep (rna rounding; QKV concat)
    round_copy_cat<<<dim3(CC/(256*4), CC), 256>>>(Wq, wqkv, CC, 0);
    round_copy_cat<<<dim3(CC/(256*4), CC), 256>>>(Wk, wqkv, CC, CC);
    round_copy_cat<<<dim3(CC/(256*4), CC), 256>>>(Wv, wqkv, CC, 2*CC);
    cat_bias<<<CC/256, 256>>>(bq, bk, bv, bqkv);
    round_copy<<<(CC*CC)/(256*4), 256>>>(Wo, wo, CC*CC);
    round_copy<<<(CC*FF)/(256*4), 256>>>(W1, w1, CC*FF);
    round_copy<<<(FF*CC)/(256*4), 256>>>(W2, w2, FF*CC);

    dim3 gQKV(3*CC / 128, ROWS / 128);  // (24, 64)
    dim3 gC(CC / 128, ROWS / 128);      // (8, 64)
    dim3 gF(FF / 128, ROWS / 128);      // (32, 64)

    // 1) LN1
    ln_kernel<<<ROWS, 256>>>(x, ln1_g, ln1_b, h);
    // 2) fused QKV projection
    gemm_tc<0><<<gQKV, 256, GEMM_SMEM>>>(h, wqkv, bqkv, nullptr, q, k, v,
                                         ROWS, 3*CC, CC, CC);
    // 3) causal attention
    attn_tc_kernel<<<dim3(TT / 64, NH, BB), 128>>>(q, k, v, y);
    // 4) output projection + residual
    gemm_tc<1><<<gC, 256, GEMM_SMEM>>>(y, wo, bo, x, x1, x1, x1,
                                       ROWS, CC, CC, CC);
    // 5) LN2
    ln_kernel<<<ROWS, 256>>>(x1, ln2_g, ln2_b, h);
    // 6) MLP
    gemm_tc<2><<<gF, 256, GEMM_SMEM>>>(h, w1, b1, nullptr, m, m, m,
                                       ROWS, FF, CC, FF);
    gemm_tc<1><<<gC, 256, GEMM_SMEM>>>(m, w2, b2, x1, out, out, out,
                                       ROWS, CC, FF, CC);
}

// round 8
// speedup vs baseline: 3.4651x; 1.0086x over previous
#include <cuda_runtime.h>
#include <cuda_bf16.h>
#include <math.h>
#include <stdint.h>

// Problem constants
#define BB   4
#define TT   2048
#define CC   1024
#define NH   16
#define DH   64
#define ROWS (BB * TT)        // 8192
#define FF   (4 * CC)         // 4096

// ---------------- scratch (no allocs allowed) ----------------
__device__ float g_h [ROWS * CC];
__device__ float g_q [ROWS * CC];
__device__ float g_k [ROWS * CC];
__device__ float g_v [ROWS * CC];
__device__ float g_y [ROWS * CC];
__device__ float g_x1[ROWS * CC];
__device__ float g_m [ROWS * FF];
// rna-rounded weight copies
__device__ float g_wqkv[CC * 3 * CC];   // [K=1024][N=3072] (Wq|Wk|Wv)
__device__ float g_bqkv[3 * CC];
__device__ float g_wo  [CC * CC];
__device__ float g_w1  [CC * FF];
__device__ float g_w2  [FF * CC];

// ---------------- common helpers ----------------
__device__ __forceinline__ float gelu_exact(float x) {
    return 0.5f * x * (1.0f + erff(x * 0.70710678118654752f));
}

__device__ __forceinline__ float cvt_tf32(float x) {
    uint32_t r;
    asm("cvt.rna.tf32.f32 %0, %1;" : "=r"(r) : "f"(x));
    return __uint_as_float(r);
}

__device__ __forceinline__ void mma_tf32(float& d0, float& d1, float& d2, float& d3,
                                         uint32_t a0, uint32_t a1, uint32_t a2, uint32_t a3,
                                         uint32_t b0, uint32_t b1) {
    asm volatile(
        "mma.sync.aligned.m16n8k8.row.col.f32.tf32.tf32.f32 "
        "{%0,%1,%2,%3}, {%4,%5,%6,%7}, {%8,%9}, {%0,%1,%2,%3};"
        : "+f"(d0), "+f"(d1), "+f"(d2), "+f"(d3)
        : "r"(a0), "r"(a1), "r"(a2), "r"(a3), "r"(b0), "r"(b1));
}

#define CP_ASYNC16(dst, src) \
    asm volatile("cp.async.cg.shared.global [%0], [%1], 16;\n" :: "r"(dst), "l"(src))
#define CP_COMMIT() asm volatile("cp.async.commit_group;\n" ::: "memory")

// ---------------- weight prep: rna-rounded copy ----------------
__global__ void round_copy(const float* __restrict__ src, float* __restrict__ dst,
                           int n) {
    int i = (blockIdx.x * blockDim.x + threadIdx.x) * 4;
    if (i < n) {
        float4 v = *(const float4*)(src + i);
        v.x = cvt_tf32(v.x); v.y = cvt_tf32(v.y);
        v.z = cvt_tf32(v.z); v.w = cvt_tf32(v.w);
        *(float4*)(dst + i) = v;
    }
}

__global__ void round_copy_cat(const float* __restrict__ src, float* __restrict__ dst,
                               int K, int coloff) {
    int k = blockIdx.y;
    int n = (blockIdx.x * blockDim.x + threadIdx.x) * 4;
    float4 v = *(const float4*)(src + (size_t)k * CC + n);
    v.x = cvt_tf32(v.x); v.y = cvt_tf32(v.y);
    v.z = cvt_tf32(v.z); v.w = cvt_tf32(v.w);
    *(float4*)(dst + (size_t)k * (3 * CC) + coloff + n) = v;
}

__global__ void cat_bias(const float* __restrict__ b0, const float* __restrict__ b1,
                         const float* __restrict__ b2, float* __restrict__ dst) {
    int i = blockIdx.x * blockDim.x + threadIdx.x;
    dst[i]          = b0[i];
    dst[i + CC]     = b1[i];
    dst[i + 2 * CC] = b2[i];
}

// ---------------- LayerNorm: one block per row (rna-rounded out) --------------
__global__ void ln_kernel(const float* __restrict__ X,
                          const float* __restrict__ gam,
                          const float* __restrict__ bet,
                          float* __restrict__ out) {
    int row = blockIdx.x;
    int tid = threadIdx.x;
    const float4* x4 = (const float4*)(X + (size_t)row * CC);
    float4 v = x4[tid];
    float s  = v.x + v.y + v.z + v.w;
    float ss = v.x*v.x + v.y*v.y + v.z*v.z + v.w*v.w;
    #pragma unroll
    for (int off = 16; off > 0; off >>= 1) {
        s  += __shfl_down_sync(0xffffffffu, s,  off);
        ss += __shfl_down_sync(0xffffffffu, ss, off);
    }
    __shared__ float smS[8], smQ[8];
    __shared__ float sh_mu, sh_rstd;
    int lane = tid & 31, w = tid >> 5;
    if (lane == 0) { smS[w] = s; smQ[w] = ss; }
    __syncthreads();
    if (tid == 0) {
        float ts = 0.f, tq = 0.f;
        #pragma unroll
        for (int i = 0; i < 8; i++) { ts += smS[i]; tq += smQ[i]; }
        float mu  = ts * (1.0f / CC);
        float var = tq * (1.0f / CC) - mu * mu;
        sh_mu = mu;
        sh_rstd = rsqrtf(var + 1e-5f);
    }
    __syncthreads();
    float mu = sh_mu, rstd = sh_rstd;
    float4 gv = ((const float4*)gam)[tid];
    float4 bv = ((const float4*)bet)[tid];
    float4 o;
    o.x = cvt_tf32((v.x - mu) * rstd * gv.x + bv.x);
    o.y = cvt_tf32((v.y - mu) * rstd * gv.y + bv.y);
    o.z = cvt_tf32((v.z - mu) * rstd * gv.z + bv.z);
    o.w = cvt_tf32((v.w - mu) * rstd * gv.w + bv.w);
    ((float4*)(out + (size_t)row * CC))[tid] = o;
}

// ---------------- TF32 HMMA GEMM, 3-stage cp.async pipeline ----------------
#define AST 20
#define WST 132
#define GST 3
#define STG_FLOATS (128 * AST + 16 * WST)   // 4672
#define GEMM_SMEM  (GST * STG_FLOATS * 4)   // 56064 bytes

template <int EPI>
__global__ __launch_bounds__(256, 2)
void gemm_tc(const float* __restrict__ A, const float* __restrict__ W,
             const float* __restrict__ bias, const float* __restrict__ res,
             float* __restrict__ C0, float* __restrict__ C1, float* __restrict__ C2,
             int M, int N, int K, int outN) {
    extern __shared__ __align__(16) float dsm[];

    int tid  = threadIdx.x;
    int lane = tid & 31;
    int wid  = tid >> 5;
    int warp_m = wid >> 2;
    int warp_n = wid & 3;
    int g = lane >> 2, t = lane & 3;
    int bm = blockIdx.y * 128;
    int bn = blockIdx.x * 128;

    int bi = bn / outN;
    float* C = (bi == 0) ? C0 : ((bi == 1) ? C1 : C2);
    int cn = bn - bi * outN;

    int am  = tid >> 2;
    int akq = (tid & 3) * 4;
    int wk  = tid >> 5;
    int wn4 = (tid & 31) * 4;

    const float* Apb = A + (size_t)(bm + am) * K + akq;
    const float* Wpb = W + (size_t)wk * N + bn + wn4;

    uint32_t sA0[GST], sA1[GST], sW0[GST], sW1[GST];
    #pragma unroll
    for (int s = 0; s < GST; s++) {
        float* base = dsm + s * STG_FLOATS;
        float (*As)[AST] = (float(*)[AST])base;
        float (*Ws)[WST] = (float(*)[WST])(base + 128 * AST);
        sA0[s] = (uint32_t)__cvta_generic_to_shared(&As[am     ][akq]);
        sA1[s] = (uint32_t)__cvta_generic_to_shared(&As[am + 64][akq]);
        sW0[s] = (uint32_t)__cvta_generic_to_shared(&Ws[wk    ][wn4]);
        sW1[s] = (uint32_t)__cvta_generic_to_shared(&Ws[wk + 8][wn4]);
    }

    float acc[4][4][4];
    #pragma unroll
    for (int i = 0; i < 4; i++)
        #pragma unroll
        for (int j = 0; j < 4; j++)
            #pragma unroll
            for (int r = 0; r < 4; r++) acc[i][j][r] = 0.f;

    int NT = K >> 4;

    #pragma unroll
    for (int s = 0; s < GST - 1; s++) {
        int k0 = s << 4;
        CP_ASYNC16(sA0[s], Apb + k0);
        CP_ASYNC16(sA1[s], Apb + (size_t)64 * K + k0);
        CP_ASYNC16(sW0[s], Wpb + (size_t)k0 * N);
        CP_ASYNC16(sW1[s], Wpb + (size_t)(k0 + 8) * N);
        CP_COMMIT();
    }

    for (int kt = 0; kt < NT; kt++) {
        int st = kt % GST;
        asm volatile("cp.async.wait_group 1;" ::: "memory");
        __syncthreads();

        if (kt + GST - 1 < NT) {
            int ns = (kt + GST - 1) % GST;
            int k0 = (kt + GST - 1) << 4;
            CP_ASYNC16(sA0[ns], Apb + k0);
            CP_ASYNC16(sA1[ns], Apb + (size_t)64 * K + k0);
            CP_ASYNC16(sW0[ns], Wpb + (size_t)k0 * N);
            CP_ASYNC16(sW1[ns], Wpb + (size_t)(k0 + 8) * N);
        }
        CP_COMMIT();

        float* base = dsm + st * STG_FLOATS;
        float (*As)[AST] = (float(*)[AST])base;
        float (*Ws)[WST] = (float(*)[WST])(base + 128 * AST);

        #pragma unroll
        for (int kc = 0; kc < 2; kc++) {
            int kr = kc * 8 + t;
            uint32_t af[4][4];
            uint32_t bf[4][2];
            #pragma unroll
            for (int mtl = 0; mtl < 4; mtl++) {
                int m = warp_m * 64 + mtl * 16 + g;
                af[mtl][0] = __float_as_uint(As[m    ][kr    ]);
                af[mtl][1] = __float_as_uint(As[m + 8][kr    ]);
                af[mtl][2] = __float_as_uint(As[m    ][kr + 4]);
                af[mtl][3] = __float_as_uint(As[m + 8][kr + 4]);
            }
            #pragma unroll
            for (int ntl = 0; ntl < 4; ntl++) {
                int n = warp_n * 32 + ntl * 8 + g;
                bf[ntl][0] = __float_as_uint(Ws[kr    ][n]);
                bf[ntl][1] = __float_as_uint(Ws[kr + 4][n]);
            }
            #pragma unroll
            for (int mtl = 0; mtl < 4; mtl++)
                #pragma unroll
                for (int ntl = 0; ntl < 4; ntl++)
                    mma_tf32(acc[mtl][ntl][0], acc[mtl][ntl][1],
                             acc[mtl][ntl][2], acc[mtl][ntl][3],
                             af[mtl][0], af[mtl][1], af[mtl][2], af[mtl][3],
                             bf[ntl][0], bf[ntl][1]);
        }
    }

    #pragma unroll
    for (int mt = 0; mt < 4; mt++) {
        int r0 = bm + warp_m * 64 + mt * 16 + g;
        #pragma unroll
        for (int nt = 0; nt < 4; nt++) {
            int gcol = bn + warp_n * 32 + nt * 8 + t * 2;
            int col  = cn + warp_n * 32 + nt * 8 + t * 2;
            float b0 = bias[gcol], b1 = bias[gcol + 1];
            #pragma unroll
            for (int h = 0; h < 2; h++) {
                int row = r0 + h * 8;
                float v0 = acc[mt][nt][h * 2 + 0] + b0;
                float v1 = acc[mt][nt][h * 2 + 1] + b1;
                if (EPI == 1) {
                    const float* rp = res + (size_t)row * outN + col;
                    v0 += rp[0]; v1 += rp[1];
                }
                if (EPI == 2) {
                    v0 = cvt_tf32(gelu_exact(v0));
                    v1 = cvt_tf32(gelu_exact(v1));
                }
                *(float2*)(C + (size_t)row * outN + col) = make_float2(v0, v1);
            }
        }
    }
}

// ---------------- Tensor-core flash attention (causal, tf32) ----------------
// Register-pipelined K/V: store tile kt from regs, issue LDGs for kt+1, compute.
#define KS_STR 68
#define VS_STR 72

__global__ __launch_bounds__(128)
void attn_tc_kernel(const float* __restrict__ Q,
                    const float* __restrict__ K,
                    const float* __restrict__ V,
                    float* __restrict__ Y) {
    __shared__ float KPs[64][KS_STR];
    __shared__ float Vs [64][VS_STR];

    int qt = blockIdx.x, h = blockIdx.y, b = blockIdx.z;
    int tid = threadIdx.x;
    int lane = tid & 31, w = tid >> 5;
    int g = lane >> 2, t = lane & 3;
    int qbase = qt * 64;
    const int hoff = h * DH;

    int lrow = tid >> 1;            // staging row for this thread
    int ld0  = (tid & 1) * 32;      // staging col offset

    // ---- stage Q (scaled, rna) via smem, capture fragments ----
    {
        const float* qp = Q + (size_t)(b * TT + qbase + lrow) * CC + hoff + ld0;
        #pragma unroll
        for (int i = 0; i < 8; i++) {
            float4 v4 = ((const float4*)qp)[i];
            KPs[lrow][ld0 + 4*i + 0] = cvt_tf32(v4.x * 0.125f);
            KPs[lrow][ld0 + 4*i + 1] = cvt_tf32(v4.y * 0.125f);
            KPs[lrow][ld0 + 4*i + 2] = cvt_tf32(v4.z * 0.125f);
            KPs[lrow][ld0 + 4*i + 3] = cvt_tf32(v4.w * 0.125f);
        }
    }
    __syncthreads();
    uint32_t qf[8][4];
    {
        int rA = 16 * w + g;
        #pragma unroll
        for (int kc = 0; kc < 8; kc++) {
            qf[kc][0] = __float_as_uint(KPs[rA    ][kc*8 + t    ]);
            qf[kc][1] = __float_as_uint(KPs[rA + 8][kc*8 + t    ]);
            qf[kc][2] = __float_as_uint(KPs[rA    ][kc*8 + t + 4]);
            qf[kc][3] = __float_as_uint(KPs[rA + 8][kc*8 + t + 4]);
        }
    }
    __syncthreads();

    float o[8][4];
    #pragma unroll
    for (int nt = 0; nt < 8; nt++)
        #pragma unroll
        for (int j = 0; j < 4; j++) o[nt][j] = 0.f;
    float mA = -1e30f, mB = -1e30f, lA = 0.f, lB = 0.f;

    // ---- prefetch tile 0 into registers ----
    float4 kr[8], vr[8];
    {
        const float4* kp = (const float4*)(K + (size_t)(b * TT + lrow) * CC + hoff + ld0);
        const float4* vp = (const float4*)(V + (size_t)(b * TT + lrow) * CC + hoff + ld0);
        #pragma unroll
        for (int i = 0; i < 8; i++) { kr[i] = kp[i]; vr[i] = vp[i]; }
    }

    for (int kt = 0; kt <= qt; kt++) {
        // ---- store current tile regs -> smem (rna) ----
        #pragma unroll
        for (int i = 0; i < 8; i++) {
            float4 kv = kr[i];
            KPs[lrow][ld0 + 4*i + 0] = cvt_tf32(kv.x);
            KPs[lrow][ld0 + 4*i + 1] = cvt_tf32(kv.y);
            KPs[lrow][ld0 + 4*i + 2] = cvt_tf32(kv.z);
            KPs[lrow][ld0 + 4*i + 3] = cvt_tf32(kv.w);
            float4 vv = vr[i];
            Vs[lrow][ld0 + 4*i + 0] = cvt_tf32(vv.x);
            Vs[lrow][ld0 + 4*i + 1] = cvt_tf32(vv.y);
            Vs[lrow][ld0 + 4*i + 2] = cvt_tf32(vv.z);
            Vs[lrow][ld0 + 4*i + 3] = cvt_tf32(vv.w);
        }
        __syncthreads();

        // ---- issue prefetch for next tile (latency hides under compute) ----
        if (kt < qt) {
            const float4* kp = (const float4*)(K + (size_t)(b * TT + (kt+1) * 64 + lrow) * CC + hoff + ld0);
            const float4* vp = (const float4*)(V + (size_t)(b * TT + (kt+1) * 64 + lrow) * CC + hoff + ld0);
            #pragma unroll
            for (int i = 0; i < 8; i++) { kr[i] = kp[i]; vr[i] = vp[i]; }
        }

        // ---- S = Q K^T ----
        float s[8][4];
        #pragma unroll
        for (int nt = 0; nt < 8; nt++)
            #pragma unroll
            for (int j = 0; j < 4; j++) s[nt][j] = 0.f;
        #pragma unroll
        for (int kc = 0; kc < 8; kc++) {
            #pragma unroll
            for (int nt = 0; nt < 8; nt++) {
                uint32_t b0 = __float_as_uint(KPs[nt*8 + g][kc*8 + t    ]);
                uint32_t b1 = __float_as_uint(KPs[nt*8 + g][kc*8 + t + 4]);
                mma_tf32(s[nt][0], s[nt][1], s[nt][2], s[nt][3],
                         qf[kc][0], qf[kc][1], qf[kc][2], qf[kc][3], b0, b1);
            }
        }

        int rA = 16 * w + g;
        int rB = rA + 8;

        if (kt == qt) {
            #pragma unroll
            for (int nt = 0; nt < 8; nt++) {
                int c0 = nt * 8 + 2 * t;
                if (c0     > rA) s[nt][0] = -1e30f;
                if (c0 + 1 > rA) s[nt][1] = -1e30f;
                if (c0     > rB) s[nt][2] = -1e30f;
                if (c0 + 1 > rB) s[nt][3] = -1e30f;
            }
        }

        float mxA = -1e30f, mxB = -1e30f;
        #pragma unroll
        for (int nt = 0; nt < 8; nt++) {
            mxA = fmaxf(mxA, fmaxf(s[nt][0], s[nt][1]));
            mxB = fmaxf(mxB, fmaxf(s[nt][2], s[nt][3]));
        }
        mxA = fmaxf(mxA, __shfl_xor_sync(0xffffffffu, mxA, 1));
        mxA = fmaxf(mxA, __shfl_xor_sync(0xffffffffu, mxA, 2));
        mxB = fmaxf(mxB, __shfl_xor_sync(0xffffffffu, mxB, 1));
        mxB = fmaxf(mxB, __shfl_xor_sync(0xffffffffu, mxB, 2));
        float mnA = fmaxf(mA, mxA);
        float mnB = fmaxf(mB, mxB);
        float corrA = __expf(mA - mnA);
        float corrB = __expf(mB - mnB);

        float sumA = 0.f, sumB = 0.f;
        #pragma unroll
        for (int nt = 0; nt < 8; nt++) {
            s[nt][0] = __expf(s[nt][0] - mnA); sumA += s[nt][0];
            s[nt][1] = __expf(s[nt][1] - mnA); sumA += s[nt][1];
            s[nt][2] = __expf(s[nt][2] - mnB); sumB += s[nt][2];
            s[nt][3] = __expf(s[nt][3] - mnB); sumB += s[nt][3];
        }
        sumA += __shfl_xor_sync(0xffffffffu, sumA, 1);
        sumA += __shfl_xor_sync(0xffffffffu, sumA, 2);
        sumB += __shfl_xor_sync(0xffffffffu, sumB, 1);
        sumB += __shfl_xor_sync(0xffffffffu, sumB, 2);
        lA = lA * corrA + sumA;
        lB = lB * corrB + sumB;
        mA = mnA; mB = mnB;

        #pragma unroll
        for (int nt = 0; nt < 8; nt++) {
            o[nt][0] *= corrA; o[nt][1] *= corrA;
            o[nt][2] *= corrB; o[nt][3] *= corrB;
        }

        __syncthreads();    // all warps done reading K from KPs
        #pragma unroll
        for (int nt = 0; nt < 8; nt++) {
            int c0 = nt * 8 + 2 * t;
            KPs[rA][c0    ] = cvt_tf32(s[nt][0]);
            KPs[rA][c0 + 1] = cvt_tf32(s[nt][1]);
            KPs[rB][c0    ] = cvt_tf32(s[nt][2]);
            KPs[rB][c0 + 1] = cvt_tf32(s[nt][3]);
        }
        __syncwarp();

        #pragma unroll
        for (int kc = 0; kc < 8; kc++) {
            uint32_t a0 = __float_as_uint(KPs[rA][kc*8 + t    ]);
            uint32_t a1 = __float_as_uint(KPs[rB][kc*8 + t    ]);
            uint32_t a2 = __float_as_uint(KPs[rA][kc*8 + t + 4]);
            uint32_t a3 = __float_as_uint(KPs[rB][kc*8 + t + 4]);
            #pragma unroll
            for (int nt = 0; nt < 8; nt++) {
                uint32_t b0 = __float_as_uint(Vs[kc*8 + t    ][nt*8 + g]);
                uint32_t b1 = __float_as_uint(Vs[kc*8 + t + 4][nt*8 + g]);
                mma_tf32(o[nt][0], o[nt][1], o[nt][2], o[nt][3],
                         a0, a1, a2, a3, b0, b1);
            }
        }
        __syncthreads();    // before overwriting KPs/Vs next iter
    }

    float invA = 1.0f / lA, invB = 1.0f / lB;
    int rowA = qbase + 16 * w + g;
    float* yA = Y + (size_t)(b * TT + rowA) * CC + hoff;
    float* yB = Y + (size_t)(b * TT + rowA + 8) * CC + hoff;
    #pragma unroll
    for (int nt = 0; nt < 8; nt++) {
        int c0 = nt * 8 + 2 * t;
        *(float2*)(yA + c0) = make_float2(cvt_tf32(o[nt][0] * invA), cvt_tf32(o[nt][1] * invA));
        *(float2*)(yB + c0) = make_float2(cvt_tf32(o[nt][2] * invB), cvt_tf32(o[nt][3] * invB));
    }
}

// ---------------- launcher ----------------
extern "C" void kernel_launch(void* const* d_in, const int* in_sizes, int n_in,
                              void* d_out, int out_size) {
    const float* x     = (const float*)d_in[0];
    const float* ln1_g = (const float*)d_in[1];
    const float* ln1_b = (const float*)d_in[2];
    const float* Wq    = (const float*)d_in[3];
    const float* bq    = (const float*)d_in[4];
    const float* Wk    = (const float*)d_in[5];
    const float* bk    = (const float*)d_in[6];
    const float* Wv    = (const float*)d_in[7];
    const float* bv    = (const float*)d_in[8];
    const float* Wo    = (const float*)d_in[9];
    const float* bo    = (const float*)d_in[10];
    const float* ln2_g = (const float*)d_in[11];
    const float* ln2_b = (const float*)d_in[12];
    const float* W1    = (const float*)d_in[13];
    const float* b1    = (const float*)d_in[14];
    const float* W2    = (const float*)d_in[15];
    const float* b2    = (const float*)d_in[16];
    float* out = (float*)d_out;

    float *h, *q, *k, *v, *y, *x1, *m;
    float *wqkv, *bqkv, *wo, *w1, *w2;
    cudaGetSymbolAddress((void**)&h,    g_h);
    cudaGetSymbolAddress((void**)&q,    g_q);
    cudaGetSymbolAddress((void**)&k,    g_k);
    cudaGetSymbolAddress((void**)&v,    g_v);
    cudaGetSymbolAddress((void**)&y,    g_y);
    cudaGetSymbolAddress((void**)&x1,   g_x1);
    cudaGetSymbolAddress((void**)&m,    g_m);
    cudaGetSymbolAddress((void**)&wqkv, g_wqkv);
    cudaGetSymbolAddress((void**)&bqkv, g_bqkv);
    cudaGetSymbolAddress((void**)&wo,   g_wo);
    cudaGetSymbolAddress((void**)&w1,   g_w1);
    cudaGetSymbolAddress((void**)&w2,   g_w2);

    cudaFuncSetAttribute(gemm_tc<0>, cudaFuncAttributeMaxDynamicSharedMemorySize, GEMM_SMEM);
    cudaFuncSetAttribute(gemm_tc<1>, cudaFuncAttributeMaxDynamicSharedMemorySize, GEMM_SMEM);
    cudaFuncSetAttribute(gemm_tc<2>, cudaFuncAttributeMaxDynamicSharedMemorySize, GEMM_SMEM);

    // 0) weight prep (rna rounding; QKV concat)
    round_copy_cat<<<dim3(CC/(256*4), CC), 256>>>(Wq, wqkv, CC, 0);
    round_copy_cat<<<dim3(CC/(256*4), CC), 256>>>(Wk, wqkv, CC, CC);
    round_copy_cat<<<dim3(CC/(256*4), CC), 256>>>(Wv, wqkv, CC, 2*CC);
    cat_bias<<<CC/256, 256>>>(bq, bk, bv, bqkv);
    round_copy<<<(CC*CC)/(256*4), 256>>>(Wo, wo, CC*CC);
    round_copy<<<(CC*FF)/(256*4), 256>>>(W1, w1, CC*FF);
    round_copy<<<(FF*CC)/(256*4), 256>>>(W2, w2, FF*CC);

    dim3 gQKV(3*CC / 128, ROWS / 128);
    dim3 gC(CC / 128, ROWS / 128);
    dim3 gF(FF / 128, ROWS / 128);

    ln_kernel<<<ROWS, 256>>>(x, ln1_g, ln1_b, h);
    gemm_tc<0><<<gQKV, 256, GEMM_SMEM>>>(h, wqkv, bqkv, nullptr, q, k, v,
                                         ROWS, 3*CC, CC, CC);
    attn_tc_kernel<<<dim3(TT / 64, NH, BB), 128>>>(q, k, v, y);
    gemm_tc<1><<<gC, 256, GEMM_SMEM>>>(y, wo, bo, x, x1, x1, x1,
                                       ROWS, CC, CC, CC);
    ln_kernel<<<ROWS, 256>>>(x1, ln2_g, ln2_b, h);
    gemm_tc<2><<<gF, 256, GEMM_SMEM>>>(h, w1, b1, nullptr, m, m, m,
                                       ROWS, FF, CC, FF);
    gemm_tc<1><<<gC, 256, GEMM_SMEM>>>(m, w2, b2, x1, out, out, out,
                                       ROWS, CC, FF, CC);
}